// round 12
// baseline (speedup 1.0000x reference)
#include <cuda_runtime.h>
#include <cuda_bf16.h>
#include <cstdint>

#define N_NODE 100000
#define N_EDGE 800000
#define EMB 128
#define PITCH 40   // bf16 elems per smem row: 32 data + 8 pad = 80 bytes

// ---------------- static device scratch (allocation-free) ----------------
__device__ float g_h0[N_NODE * EMB];
__device__ float g_h1[N_NODE * EMB];
__device__ float g_n0[N_NODE * EMB];
__device__ float g_n1[N_NODE * EMB];
__device__ float g_E11[N_NODE * EMB];
__device__ float g_E01[N_NODE * EMB];
__device__ float g_E10[N_NODE * EMB];
__device__ float g_E00[N_NODE * EMB];
__device__ float g_a11[N_NODE * EMB];
__device__ float g_cat0[N_NODE * 256];   // [agg10 | agg00]
__device__ float g_cat1[N_NODE * 384];   // [T(256) | agg01(128)]
__device__ float g_esum[4 * N_NODE * 16];
__device__ float g_deg[4 * N_NODE];
__device__ float g_stats[1024];
// pre-transposed / pre-split / pre-scaled weights: [N][K] bf16 hi/lo
__device__ __align__(16) __nv_bfloat16 g_bth[147456];
__device__ __align__(16) __nv_bfloat16 g_btl[147456];
__device__ float g_biasc[1024];

// ---------------- tiny utility kernels ----------------
__global__ void k_zero(float* __restrict__ p, int n4) {
    float4 z = make_float4(0.f, 0.f, 0.f, 0.f);
    for (int i = blockIdx.x * blockDim.x + threadIdx.x; i < n4;
         i += gridDim.x * blockDim.x)
        reinterpret_cast<float4*>(p)[i] = z;
}

__device__ __forceinline__ void red_add_v4(float* p, float4 v) {
    asm volatile("red.global.add.v4.f32 [%0], {%1,%2,%3,%4};"
                 :: "l"(p), "f"(v.x), "f"(v.y), "f"(v.z), "f"(v.w)
                 : "memory");
}
__device__ __forceinline__ void red_add_f32(float* p, float v) {
    asm volatile("red.global.add.f32 [%0], %1;" :: "l"(p), "f"(v) : "memory");
}

// ---------------- edge phase: scatter 16-wide ea sums + degree ----------------
__global__ void k_edge_sum(const float* __restrict__ ea, const int* __restrict__ dst,
                           float* __restrict__ Esum, float* __restrict__ deg) {
    const int n = N_EDGE * 4;
    for (int i = blockIdx.x * blockDim.x + threadIdx.x; i < n;
         i += gridDim.x * blockDim.x) {
        int e = i >> 2, q = i & 3;
        int d = __ldg(&dst[e]);
        float4 v = *reinterpret_cast<const float4*>(ea + (size_t)e * 16 + q * 4);
        red_add_v4(Esum + (size_t)d * 16 + q * 4, v);
        if (q == 0) red_add_f32(deg + d, 1.0f);
    }
}

// E[r] = Esum[r] @ We + deg[r]*be   (one warp per node row)
__global__ void k_edge_gemm(const float* __restrict__ Esum, const float* __restrict__ deg,
                            const float* __restrict__ We, const float* __restrict__ be,
                            float* __restrict__ Eout) {
    __shared__ float sW[16 * EMB];
    for (int i = threadIdx.x; i < 16 * EMB; i += blockDim.x) sW[i] = We[i];
    __syncthreads();
    const int lane = threadIdx.x & 31;
    const int warp = (blockIdx.x * blockDim.x + threadIdx.x) >> 5;
    const int nwarp = (gridDim.x * blockDim.x) >> 5;
    const int c0 = lane * 4;
    const float4 bev = *reinterpret_cast<const float4*>(be + c0);
    for (int r = warp; r < N_NODE; r += nwarp) {
        float av = (lane < 16) ? Esum[(size_t)r * 16 + lane] : 0.f;
        float dg = __ldg(&deg[r]);
        float4 acc = make_float4(dg * bev.x, dg * bev.y, dg * bev.z, dg * bev.w);
#pragma unroll
        for (int k = 0; k < 16; k++) {
            float a = __shfl_sync(0xffffffffu, av, k);
            float4 w = *reinterpret_cast<const float4*>(sW + k * EMB + c0);
            acc.x += a * w.x; acc.y += a * w.y; acc.z += a * w.z; acc.w += a * w.w;
        }
        *reinterpret_cast<float4*>(Eout + (size_t)r * EMB + c0) = acc;
    }
}

// ---------------- scatter: agg[dst*ldc+off] += f(h[src]) ----------------
// coef != null: f(x) = relu(coef[col]*x + coef[128+col])  (fused layer-0 BN)
__global__ void k_scatter(const float* __restrict__ h, const int* __restrict__ src,
                          const int* __restrict__ dst, float* __restrict__ agg,
                          int ldc, int coloff, const float* __restrict__ coef) {
    const int lane = threadIdx.x & 31;
    const int warp = (blockIdx.x * blockDim.x + threadIdx.x) >> 5;
    if (warp >= N_EDGE) return;
    int s = __ldg(&src[warp]);
    int d = __ldg(&dst[warp]);
    const int c0 = lane * 4;
    float4 v = *reinterpret_cast<const float4*>(h + (size_t)s * EMB + c0);
    if (coef) {
        float4 ca = *reinterpret_cast<const float4*>(coef + c0);
        float4 cb = *reinterpret_cast<const float4*>(coef + 128 + c0);
        v.x = fmaxf(ca.x * v.x + cb.x, 0.f);
        v.y = fmaxf(ca.y * v.y + cb.y, 0.f);
        v.z = fmaxf(ca.z * v.z + cb.z, 0.f);
        v.w = fmaxf(ca.w * v.w + cb.w, 0.f);
    }
    red_add_v4(agg + (size_t)d * ldc + coloff + c0, v);
}

// ---------------- fused per-layer init: cat0 <- [E10|E00], cat1[256:] <- E01,
//                  a11 <- E11 + 1.1*f(h1); f = BN-affine+relu when coef1 ----------------
__global__ void k_init_layer(float* __restrict__ cat0, float* __restrict__ cat1,
                             float* __restrict__ a11,
                             const float* __restrict__ E10, const float* __restrict__ E00,
                             const float* __restrict__ E01, const float* __restrict__ E11,
                             const float* __restrict__ h1,
                             const float* __restrict__ coef1) {
    const int n = N_NODE * 32;
    for (int i = blockIdx.x * blockDim.x + threadIdx.x; i < n;
         i += gridDim.x * blockDim.x) {
        int r = i >> 5, c = i & 31;
        reinterpret_cast<float4*>(cat0)[r * 64 + c] =
            reinterpret_cast<const float4*>(E10)[i];
        reinterpret_cast<float4*>(cat0)[r * 64 + 32 + c] =
            reinterpret_cast<const float4*>(E00)[i];
        reinterpret_cast<float4*>(cat1)[r * 96 + 64 + c] =
            reinterpret_cast<const float4*>(E01)[i];
        float4 ev = reinterpret_cast<const float4*>(E11)[i];
        float4 hv = reinterpret_cast<const float4*>(h1)[i];
        if (coef1) {
            const int c0 = c * 4;
            float4 ca = *reinterpret_cast<const float4*>(coef1 + c0);
            float4 cb = *reinterpret_cast<const float4*>(coef1 + 128 + c0);
            hv.x = fmaxf(ca.x * hv.x + cb.x, 0.f);
            hv.y = fmaxf(ca.y * hv.y + cb.y, 0.f);
            hv.z = fmaxf(ca.z * hv.z + cb.z, 0.f);
            hv.w = fmaxf(ca.w * hv.w + cb.w, 0.f);
        }
        ev.x += 1.1f * hv.x; ev.y += 1.1f * hv.y;
        ev.z += 1.1f * hv.z; ev.w += 1.1f * hv.w;
        reinterpret_cast<float4*>(a11)[i] = ev;
    }
}

// ---------------- weight prep: Bcat -> [N][K] bf16 hi/lo, scaled; combined bias ----------------
__global__ void k_prep(const float* __restrict__ B1, const float* __restrict__ B2,
                       int Kb, int K, int Ngm, int Nout, float s1, float s2,
                       const float* __restrict__ b1, const float* __restrict__ b2,
                       __nv_bfloat16* __restrict__ oh, __nv_bfloat16* __restrict__ ol,
                       float* __restrict__ ob) {
    const int tot = Nout * K;
    for (int i = blockIdx.x * blockDim.x + threadIdx.x; i < tot;
         i += gridDim.x * blockDim.x) {
        int n = i / K, k = i - n * K;
        float v = (k < Kb) ? s1 * B1[(size_t)k * Ngm + n]
                           : s2 * B2[(size_t)(k - Kb) * Ngm + n];
        __nv_bfloat16 h = __float2bfloat16(v);
        oh[i] = h;
        ol[i] = __float2bfloat16(v - __bfloat162float(h));
        if (k == 0) ob[n] = s1 * b1[n] + s2 * b2[n];
    }
}

// ---------------- warp-MMA split-bf16 GEMM (legacy HMMA path) ----------------
__device__ __forceinline__ uint32_t s2u(const void* p) {
    uint32_t a;
    asm("{ .reg .u64 t; cvta.to.shared.u64 t, %1; cvt.u32.u64 %0, t; }"
        : "=r"(a) : "l"(p));
    return a;
}
__device__ __forceinline__ void ldsm4(uint32_t* r, uint32_t addr) {
    asm volatile("ldmatrix.sync.aligned.m8n8.x4.shared.b16 {%0,%1,%2,%3}, [%4];"
                 : "=r"(r[0]), "=r"(r[1]), "=r"(r[2]), "=r"(r[3]) : "r"(addr));
}
__device__ __forceinline__ void ldsm2(uint32_t* r, uint32_t addr) {
    asm volatile("ldmatrix.sync.aligned.m8n8.x2.shared.b16 {%0,%1}, [%2];"
                 : "=r"(r[0]), "=r"(r[1]) : "r"(addr));
}
__device__ __forceinline__ void mma16816(float* c, const uint32_t* a, const uint32_t* b) {
    asm volatile(
        "mma.sync.aligned.m16n8k16.row.col.f32.bf16.bf16.f32 "
        "{%0,%1,%2,%3}, {%4,%5,%6,%7}, {%8,%9}, {%0,%1,%2,%3};"
        : "+f"(c[0]), "+f"(c[1]), "+f"(c[2]), "+f"(c[3])
        : "r"(a[0]), "r"(a[1]), "r"(a[2]), "r"(a[3]), "r"(b[0]), "r"(b[1]));
}
__device__ __forceinline__ uint32_t pk2(float a, float b) {
    __nv_bfloat162 h = __floats2bfloat162_rn(a, b);
    return *reinterpret_cast<uint32_t*>(&h);
}

// If statp != null (requires N==128, grid.x==1): accumulate output column sums
// into statp[col], sum-of-squares into statp[128+col].
__global__ __launch_bounds__(256, 2) void k_mma_gemm(
    const float* __restrict__ A, int lda, int M, int K,
    const __nv_bfloat16* __restrict__ Bh, const __nv_bfloat16* __restrict__ Bl,
    const float* __restrict__ biasc,
    float* __restrict__ C, int ldc, int relu, float* __restrict__ statp) {
    __shared__ __nv_bfloat16 sAh[128 * PITCH], sAl[128 * PITCH];
    __shared__ __nv_bfloat16 sBh[128 * PITCH], sBl[128 * PITCH];
    __shared__ float sred[256];
    const int t = threadIdx.x, lane = t & 31, wid = t >> 5;
    const int rowBase = blockIdx.y * 128;
    const int n0g = blockIdx.x * 128;
    const int wm = (wid >> 1) * 32, wn = (wid & 1) * 64;
    const uint32_t uAh = s2u(sAh), uAl = s2u(sAl);
    const uint32_t uBh = s2u(sBh), uBl = s2u(sBl);

    float acc[2][8][4];
#pragma unroll
    for (int i = 0; i < 2; i++)
#pragma unroll
        for (int j = 0; j < 8; j++)
#pragma unroll
            for (int q = 0; q < 4; q++) acc[i][j][q] = 0.f;

    const int li = lane & 7;
    const int a_row = (lane >> 3 & 1) * 8 + li;
    const int a_kof = (lane >> 4) * 8;
    const int b_row = li;
    const int b_kof = ((lane >> 3) & 1) * 8;
    const int arow = t >> 1, acol = (t & 1) * 16;

    for (int k0 = 0; k0 < K; k0 += 32) {
        {
            const int gr = rowBase + arow;
            float f[16];
            if (gr < M) {
                const float* ap = A + (size_t)gr * lda + k0 + acol;
#pragma unroll
                for (int q = 0; q < 4; q++) {
                    float4 v = __ldg(reinterpret_cast<const float4*>(ap + q * 4));
                    f[4 * q] = v.x; f[4 * q + 1] = v.y;
                    f[4 * q + 2] = v.z; f[4 * q + 3] = v.w;
                }
            } else {
#pragma unroll
                for (int q = 0; q < 16; q++) f[q] = 0.f;
            }
            uint32_t h[8], l[8];
#pragma unroll
            for (int q = 0; q < 8; q++) {
                float x0 = f[2 * q], x1 = f[2 * q + 1];
                float r0 = x0 - __bfloat162float(__float2bfloat16(x0));
                float r1 = x1 - __bfloat162float(__float2bfloat16(x1));
                h[q] = pk2(x0, x1);
                l[q] = pk2(r0, r1);
            }
            __nv_bfloat16* dh = sAh + arow * PITCH + acol;
            __nv_bfloat16* dl = sAl + arow * PITCH + acol;
            reinterpret_cast<uint4*>(dh)[0] = make_uint4(h[0], h[1], h[2], h[3]);
            reinterpret_cast<uint4*>(dh)[1] = make_uint4(h[4], h[5], h[6], h[7]);
            reinterpret_cast<uint4*>(dl)[0] = make_uint4(l[0], l[1], l[2], l[3]);
            reinterpret_cast<uint4*>(dl)[1] = make_uint4(l[4], l[5], l[6], l[7]);
        }
        {
            const int brow = t >> 1, bcol = (t & 1) * 16;
            const size_t go = (size_t)(n0g + brow) * K + k0 + bcol;
            const uint4* bhp = reinterpret_cast<const uint4*>(Bh + go);
            const uint4* blp = reinterpret_cast<const uint4*>(Bl + go);
            __nv_bfloat16* dh = sBh + brow * PITCH + bcol;
            __nv_bfloat16* dl = sBl + brow * PITCH + bcol;
            reinterpret_cast<uint4*>(dh)[0] = __ldg(bhp);
            reinterpret_cast<uint4*>(dh)[1] = __ldg(bhp + 1);
            reinterpret_cast<uint4*>(dl)[0] = __ldg(blp);
            reinterpret_cast<uint4*>(dl)[1] = __ldg(blp + 1);
        }
        __syncthreads();

#pragma unroll
        for (int ks = 0; ks < 32; ks += 16) {
            uint32_t ah[2][4], al[2][4];
#pragma unroll
            for (int mt = 0; mt < 2; mt++) {
                uint32_t off = ((wm + mt * 16 + a_row) * PITCH + ks + a_kof) * 2;
                ldsm4(ah[mt], uAh + off);
                ldsm4(al[mt], uAl + off);
            }
#pragma unroll
            for (int nt = 0; nt < 8; nt++) {
                uint32_t bh[2], bl[2];
                uint32_t off = ((wn + nt * 8 + b_row) * PITCH + ks + b_kof) * 2;
                ldsm2(bh, uBh + off);
                ldsm2(bl, uBl + off);
#pragma unroll
                for (int mt = 0; mt < 2; mt++) {
                    mma16816(acc[mt][nt], ah[mt], bh);
                    mma16816(acc[mt][nt], ah[mt], bl);
                    mma16816(acc[mt][nt], al[mt], bh);
                }
            }
        }
        __syncthreads();
    }

    if (statp) {
        sred[t] = 0.f;
        __syncthreads();
    }

    const int r4 = lane >> 2, c2 = (lane & 3) * 2;
#pragma unroll
    for (int mt = 0; mt < 2; mt++) {
        const int row0 = rowBase + wm + mt * 16 + r4;
        const int row1 = row0 + 8;
#pragma unroll
        for (int nt = 0; nt < 8; nt++) {
            const int col = n0g + wn + nt * 8 + c2;
            float b0 = __ldg(biasc + col), b1 = __ldg(biasc + col + 1);
            float v0 = acc[mt][nt][0] + b0, v1 = acc[mt][nt][1] + b1;
            float v2 = acc[mt][nt][2] + b0, v3 = acc[mt][nt][3] + b1;
            if (relu) {
                v0 = fmaxf(v0, 0.f); v1 = fmaxf(v1, 0.f);
                v2 = fmaxf(v2, 0.f); v3 = fmaxf(v3, 0.f);
            }
            if (row0 < M)
                *reinterpret_cast<float2*>(C + (size_t)row0 * ldc + col) =
                    make_float2(v0, v1);
            if (row1 < M)
                *reinterpret_cast<float2*>(C + (size_t)row1 * ldc + col) =
                    make_float2(v2, v3);
            if (statp) {
                float s0 = 0.f, q0 = 0.f, s1 = 0.f, q1 = 0.f;
                if (row0 < M) { s0 += v0; q0 += v0 * v0; s1 += v1; q1 += v1 * v1; }
                if (row1 < M) { s0 += v2; q0 += v2 * v2; s1 += v3; q1 += v3 * v3; }
                const int lc = wn + nt * 8 + c2;   // grid.x==1 -> lc == col
                atomicAdd(&sred[lc], s0);
                atomicAdd(&sred[128 + lc], q0);
                atomicAdd(&sred[lc + 1], s1);
                atomicAdd(&sred[128 + lc + 1], q1);
            }
        }
    }

    if (statp) {
        __syncthreads();
        if (t < 128) {
            atomicAdd(&statp[t], sred[t]);
            atomicAdd(&statp[128 + t], sred[128 + t]);
        }
    }
}

// ---------------- BatchNorm finalize / final apply ----------------
__global__ void k_bn_finalize(float* __restrict__ stats, const float* __restrict__ gamma,
                              const float* __restrict__ beta, int layer, float invM) {
    int c = threadIdx.x;
    int type = c >> 7, col = c & 127;
    float mu = stats[type * 256 + col] * invM;
    float var = stats[type * 256 + 128 + col] * invM - mu * mu;
    float a = gamma[layer * EMB + col] * rsqrtf(var + 1e-5f);
    float b = beta[layer * EMB + col] - a * mu;
    stats[512 + type * 256 + col] = a;
    stats[512 + type * 256 + 128 + col] = b;
}

__global__ void k_bn_apply2(const float* __restrict__ X0, float* __restrict__ Y0,
                            const float* __restrict__ X1, float* __restrict__ Y1,
                            const float* __restrict__ stats, int relu) {
    const int n = N_NODE * EMB;
    for (int i = blockIdx.x * blockDim.x + threadIdx.x; i < 2 * n;
         i += gridDim.x * blockDim.x) {
        int col = i & 127;
        if (i < n) {
            float v = stats[512 + col] * X0[i] + stats[512 + 128 + col];
            if (relu) v = fmaxf(v, 0.f);
            Y0[i] = v;
        } else {
            int j = i - n;
            float v = stats[768 + col] * X1[j] + stats[768 + 128 + col];
            if (relu) v = fmaxf(v, 0.f);
            Y1[j] = v;
        }
    }
}

// ---------------- host orchestration ----------------
extern "C" void kernel_launch(void* const* d_in, const int* in_sizes, int n_in,
                              void* d_out, int out_size) {
    (void)in_sizes; (void)n_in; (void)out_size;
    const float* x0   = (const float*)d_in[0];
    const float* x1   = (const float*)d_in[1];
    const float* ea11 = (const float*)d_in[2];
    const float* ea10 = (const float*)d_in[3];
    const float* ea01 = (const float*)d_in[4];
    const float* ea00 = (const float*)d_in[5];
    const int*   ei11 = (const int*)d_in[6];
    const int*   ei10 = (const int*)d_in[7];
    const int*   ei01 = (const int*)d_in[8];
    const int*   ei00 = (const int*)d_in[9];
    const float* Wx  = (const float*)d_in[10];
    const float* bx  = (const float*)d_in[11];
    const float* We  = (const float*)d_in[12];
    const float* be  = (const float*)d_in[13];
    const float* gW1 = (const float*)d_in[14];
    const float* gb1 = (const float*)d_in[15];
    const float* gW2 = (const float*)d_in[16];
    const float* gb2 = (const float*)d_in[17];
    const float* W10 = (const float*)d_in[18];
    const float* b10 = (const float*)d_in[19];
    const float* W01 = (const float*)d_in[20];
    const float* b01 = (const float*)d_in[21];
    const float* W00 = (const float*)d_in[22];
    const float* b00 = (const float*)d_in[23];
    const float* gamma = (const float*)d_in[24];
    const float* beta  = (const float*)d_in[25];
    float* out = (float*)d_out;

    float *h0, *h1, *n0b, *n1b, *E11, *E01, *E10, *E00, *a11, *cat0, *cat1;
    float *esum, *deg, *stats, *biasc;
    __nv_bfloat16 *bth, *btl;
    cudaGetSymbolAddress((void**)&h0,   g_h0);
    cudaGetSymbolAddress((void**)&h1,   g_h1);
    cudaGetSymbolAddress((void**)&n0b,  g_n0);
    cudaGetSymbolAddress((void**)&n1b,  g_n1);
    cudaGetSymbolAddress((void**)&E11,  g_E11);
    cudaGetSymbolAddress((void**)&E01,  g_E01);
    cudaGetSymbolAddress((void**)&E10,  g_E10);
    cudaGetSymbolAddress((void**)&E00,  g_E00);
    cudaGetSymbolAddress((void**)&a11,  g_a11);
    cudaGetSymbolAddress((void**)&cat0, g_cat0);
    cudaGetSymbolAddress((void**)&cat1, g_cat1);
    cudaGetSymbolAddress((void**)&esum, g_esum);
    cudaGetSymbolAddress((void**)&deg,  g_deg);
    cudaGetSymbolAddress((void**)&stats, g_stats);
    cudaGetSymbolAddress((void**)&bth,  g_bth);
    cudaGetSymbolAddress((void**)&btl,  g_btl);
    cudaGetSymbolAddress((void**)&biasc, g_biasc);

    // ---- weight prep ----
    k_prep<<<128, 256>>>(Wx, Wx, 256, 256, 128, 128, 1.f, 0.f, bx, bx,
                         bth, btl, biasc);
    k_prep<<<128, 256>>>(gW1, gW1, 128, 128, 256, 256, 1.f, 0.f, gb1, gb1,
                         bth + 32768, btl + 32768, biasc + 256);
    k_prep<<<192, 256>>>(gW2, W01, 256, 384, 128, 128, 0.5f, 0.05f, gb2, b01,
                         bth + 65536, btl + 65536, biasc + 512);
    k_prep<<<128, 256>>>(W10, W00, 128, 256, 128, 128, 0.05f, 0.05f, b10, b00,
                         bth + 114688, btl + 114688, biasc + 768);

    // ---- edge phase: 16-wide sums + degree, then tiny GEMV per node ----
    k_zero<<<2048, 256>>>(esum, 4 * N_NODE * 4);
    k_zero<<<512, 256>>>(deg, N_NODE);
    k_edge_sum<<<1600, 256>>>(ea11, ei11 + N_EDGE, esum + 0 * N_NODE * 16, deg + 0 * N_NODE);
    k_edge_sum<<<1600, 256>>>(ea01, ei01 + N_EDGE, esum + 1 * N_NODE * 16, deg + 1 * N_NODE);
    k_edge_sum<<<1600, 256>>>(ea10, ei10 + N_EDGE, esum + 2 * N_NODE * 16, deg + 2 * N_NODE);
    k_edge_sum<<<1600, 256>>>(ea00, ei00 + N_EDGE, esum + 3 * N_NODE * 16, deg + 3 * N_NODE);
    k_edge_gemm<<<1024, 256>>>(esum + 0 * N_NODE * 16, deg + 0 * N_NODE, We, be, E11);
    k_edge_gemm<<<1024, 256>>>(esum + 1 * N_NODE * 16, deg + 1 * N_NODE, We, be, E01);
    k_edge_gemm<<<1024, 256>>>(esum + 2 * N_NODE * 16, deg + 2 * N_NODE, We, be, E10);
    k_edge_gemm<<<1024, 256>>>(esum + 3 * N_NODE * 16, deg + 3 * N_NODE, We, be, E00);

    const int MT = (N_NODE + 127) / 128;   // 782 row tiles
    dim3 gg1(1, MT), gg2(2, MT);

    // Input embeddings: h = x @ Wx + bx
    k_mma_gemm<<<gg1, 256>>>(x0, 256, N_NODE, 256, bth, btl, biasc, h0, 128, 0, nullptr);
    k_mma_gemm<<<gg1, 256>>>(x1, 256, N_NODE, 256, bth, btl, biasc, h1, 128, 0, nullptr);

    const int sgrid = (N_EDGE * 32) / 256;  // 1 warp per edge

    // =================== layer 0 ===================
    k_init_layer<<<2048, 256>>>(cat0, cat1, a11, E10, E00, E01, E11, h1, nullptr);
    k_scatter<<<sgrid, 256>>>(h1, ei11, ei11 + N_EDGE, a11, 128, 0, nullptr);
    k_scatter<<<sgrid, 256>>>(h0, ei01, ei01 + N_EDGE, cat1, 384, 256, nullptr);
    k_scatter<<<sgrid, 256>>>(h1, ei10, ei10 + N_EDGE, cat0, 256, 0, nullptr);
    k_scatter<<<sgrid, 256>>>(h0, ei00, ei00 + N_EDGE, cat0, 256, 128, nullptr);

    k_zero<<<1, 128>>>(stats, 128);   // zero sums region [0,512)
    k_mma_gemm<<<gg2, 256>>>(a11, 128, N_NODE, 128,
                             bth + 32768, btl + 32768, biasc + 256,
                             cat1, 384, 1, nullptr);
    k_mma_gemm<<<gg1, 256>>>(cat1, 384, N_NODE, 384,
                             bth + 65536, btl + 65536, biasc + 512,
                             n1b, 128, 0, stats + 256);
    k_mma_gemm<<<gg1, 256>>>(cat0, 256, N_NODE, 256,
                             bth + 114688, btl + 114688, biasc + 768,
                             n0b, 128, 0, stats);
    k_bn_finalize<<<1, 256>>>(stats, gamma, beta, 0, 1.f / N_NODE);
    // NOTE: layer-0 bn_apply+relu is fused into layer-1 consumers below.

    // =================== layer 1 ===================
    k_init_layer<<<2048, 256>>>(cat0, cat1, a11, E10, E00, E01, E11, n1b,
                                stats + 768);
    k_scatter<<<sgrid, 256>>>(n1b, ei11, ei11 + N_EDGE, a11, 128, 0, stats + 768);
    k_scatter<<<sgrid, 256>>>(n0b, ei01, ei01 + N_EDGE, cat1, 384, 256, stats + 512);
    k_scatter<<<sgrid, 256>>>(n1b, ei10, ei10 + N_EDGE, cat0, 256, 0, stats + 768);
    k_scatter<<<sgrid, 256>>>(n0b, ei00, ei00 + N_EDGE, cat0, 256, 128, stats + 512);

    k_zero<<<1, 128>>>(stats, 128);   // sums only; coef region [512,1024) preserved
    k_mma_gemm<<<gg2, 256>>>(a11, 128, N_NODE, 128,
                             bth + 32768, btl + 32768, biasc + 256,
                             cat1, 384, 1, nullptr);
    k_mma_gemm<<<gg1, 256>>>(cat1, 384, N_NODE, 384,
                             bth + 65536, btl + 65536, biasc + 512,
                             h1, 128, 0, stats + 256);
    k_mma_gemm<<<gg1, 256>>>(cat0, 256, N_NODE, 256,
                             bth + 114688, btl + 114688, biasc + 768,
                             h0, 128, 0, stats);
    k_bn_finalize<<<1, 256>>>(stats, gamma, beta, 1, 1.f / N_NODE);
    k_bn_apply2<<<2048, 256>>>(h0, out, h1, out + (size_t)N_NODE * EMB, stats, 0);
}

// round 13
// speedup vs baseline: 1.2098x; 1.2098x over previous
#include <cuda_runtime.h>
#include <cuda_bf16.h>
#include <cstdint>

#define N_NODE 100000
#define N_EDGE 800000
#define EMB 128
#define PITCH 40   // bf16 elems per smem row: 32 data + 8 pad = 80 bytes

// ---------------- static device scratch (allocation-free) ----------------
__device__ float g_h0[N_NODE * EMB];
__device__ float g_h1[N_NODE * EMB];
__device__ float g_n0[N_NODE * EMB];
__device__ float g_n1[N_NODE * EMB];
__device__ float g_E11[N_NODE * EMB];
__device__ float g_E01[N_NODE * EMB];
__device__ float g_E10[N_NODE * EMB];
__device__ float g_E00[N_NODE * EMB];
__device__ float g_a11[N_NODE * EMB];
__device__ float g_cat0[N_NODE * 256];   // [agg10 | agg00]
__device__ float g_cat1[N_NODE * 384];   // [T(256) | agg01(128)]
__device__ float g_esum[4 * N_NODE * 16];
__device__ float g_deg[4 * N_NODE];
__device__ float g_stats[1024];
// pre-transposed / pre-split / pre-scaled weights: [N][K] bf16 hi/lo
__device__ __align__(16) __nv_bfloat16 g_bth[147456];
__device__ __align__(16) __nv_bfloat16 g_btl[147456];
__device__ float g_biasc[1024];

// ---------------- tiny utility kernels ----------------
__global__ void k_zero(float* __restrict__ p, int n4) {
    float4 z = make_float4(0.f, 0.f, 0.f, 0.f);
    for (int i = blockIdx.x * blockDim.x + threadIdx.x; i < n4;
         i += gridDim.x * blockDim.x)
        reinterpret_cast<float4*>(p)[i] = z;
}

__device__ __forceinline__ void red_add_v4(float* p, float4 v) {
    asm volatile("red.global.add.v4.f32 [%0], {%1,%2,%3,%4};"
                 :: "l"(p), "f"(v.x), "f"(v.y), "f"(v.z), "f"(v.w)
                 : "memory");
}
__device__ __forceinline__ void red_add_f32(float* p, float v) {
    asm volatile("red.global.add.f32 [%0], %1;" :: "l"(p), "f"(v) : "memory");
}

// ---------------- merged edge phase: all 4 types in one launch ----------------
// blockIdx.y = type; scatter 16-wide ea sums + degree
__global__ void k_edge_sum4(const float* __restrict__ ea0, const int* __restrict__ d0,
                            const float* __restrict__ ea1, const int* __restrict__ d1,
                            const float* __restrict__ ea2, const int* __restrict__ d2,
                            const float* __restrict__ ea3, const int* __restrict__ d3,
                            float* __restrict__ esum, float* __restrict__ deg) {
    const int ty = blockIdx.y;
    const float* ea = (ty == 0) ? ea0 : (ty == 1) ? ea1 : (ty == 2) ? ea2 : ea3;
    const int* dst  = (ty == 0) ? d0  : (ty == 1) ? d1  : (ty == 2) ? d2  : d3;
    float* Esum = esum + (size_t)ty * N_NODE * 16;
    float* dg   = deg + (size_t)ty * N_NODE;
    const int n = N_EDGE * 4;
    for (int i = blockIdx.x * blockDim.x + threadIdx.x; i < n;
         i += gridDim.x * blockDim.x) {
        int e = i >> 2, q = i & 3;
        int d = __ldg(&dst[e]);
        float4 v = *reinterpret_cast<const float4*>(ea + (size_t)e * 16 + q * 4);
        red_add_v4(Esum + (size_t)d * 16 + q * 4, v);
        if (q == 0) red_add_f32(dg + d, 1.0f);
    }
}

// E[r] = Esum[r] @ We + deg[r]*be  (one warp per node row); blockIdx.y = type
__global__ void k_edge_gemm4(const float* __restrict__ esum, const float* __restrict__ deg,
                             const float* __restrict__ We, const float* __restrict__ be,
                             float* __restrict__ E0, float* __restrict__ E1,
                             float* __restrict__ E2, float* __restrict__ E3) {
    __shared__ float sW[16 * EMB];
    for (int i = threadIdx.x; i < 16 * EMB; i += blockDim.x) sW[i] = We[i];
    __syncthreads();
    const int ty = blockIdx.y;
    const float* Esum = esum + (size_t)ty * N_NODE * 16;
    const float* dgp  = deg + (size_t)ty * N_NODE;
    float* Eout = (ty == 0) ? E0 : (ty == 1) ? E1 : (ty == 2) ? E2 : E3;
    const int lane = threadIdx.x & 31;
    const int warp = (blockIdx.x * blockDim.x + threadIdx.x) >> 5;
    const int nwarp = (gridDim.x * blockDim.x) >> 5;
    const int c0 = lane * 4;
    const float4 bev = *reinterpret_cast<const float4*>(be + c0);
    for (int r = warp; r < N_NODE; r += nwarp) {
        float av = (lane < 16) ? Esum[(size_t)r * 16 + lane] : 0.f;
        float dg = __ldg(&dgp[r]);
        float4 acc = make_float4(dg * bev.x, dg * bev.y, dg * bev.z, dg * bev.w);
#pragma unroll
        for (int k = 0; k < 16; k++) {
            float a = __shfl_sync(0xffffffffu, av, k);
            float4 w = *reinterpret_cast<const float4*>(sW + k * EMB + c0);
            acc.x += a * w.x; acc.y += a * w.y; acc.z += a * w.z; acc.w += a * w.w;
        }
        *reinterpret_cast<float4*>(Eout + (size_t)r * EMB + c0) = acc;
    }
}

// ---------------- per-layer node gather/scatter ----------------
__global__ void k_scatter(const float* __restrict__ h, const int* __restrict__ src,
                          const int* __restrict__ dst, float* __restrict__ agg,
                          int ldc, int coloff) {
    const int lane = threadIdx.x & 31;
    const int warp = (blockIdx.x * blockDim.x + threadIdx.x) >> 5;
    if (warp >= N_EDGE) return;
    int s = __ldg(&src[warp]);
    int d = __ldg(&dst[warp]);
    float4 v = *reinterpret_cast<const float4*>(h + (size_t)s * EMB + lane * 4);
    red_add_v4(agg + (size_t)d * ldc + coloff + lane * 4, v);
}

// ---------------- fused per-layer init ----------------
__global__ void k_init_layer(float* __restrict__ cat0, float* __restrict__ cat1,
                             float* __restrict__ a11,
                             const float* __restrict__ E10, const float* __restrict__ E00,
                             const float* __restrict__ E01, const float* __restrict__ E11,
                             const float* __restrict__ h1) {
    const int n = N_NODE * 32;
    for (int i = blockIdx.x * blockDim.x + threadIdx.x; i < n;
         i += gridDim.x * blockDim.x) {
        int r = i >> 5, c = i & 31;
        reinterpret_cast<float4*>(cat0)[r * 64 + c] =
            reinterpret_cast<const float4*>(E10)[i];
        reinterpret_cast<float4*>(cat0)[r * 64 + 32 + c] =
            reinterpret_cast<const float4*>(E00)[i];
        reinterpret_cast<float4*>(cat1)[r * 96 + 64 + c] =
            reinterpret_cast<const float4*>(E01)[i];
        float4 ev = reinterpret_cast<const float4*>(E11)[i];
        float4 hv = reinterpret_cast<const float4*>(h1)[i];
        ev.x += 1.1f * hv.x; ev.y += 1.1f * hv.y;
        ev.z += 1.1f * hv.z; ev.w += 1.1f * hv.w;
        reinterpret_cast<float4*>(a11)[i] = ev;
    }
}

// ---------------- weight prep: Bcat -> [N][K] bf16 hi/lo, scaled; combined bias ----------------
__global__ void k_prep(const float* __restrict__ B1, const float* __restrict__ B2,
                       int Kb, int K, int Ngm, int Nout, float s1, float s2,
                       const float* __restrict__ b1, const float* __restrict__ b2,
                       __nv_bfloat16* __restrict__ oh, __nv_bfloat16* __restrict__ ol,
                       float* __restrict__ ob) {
    const int tot = Nout * K;
    for (int i = blockIdx.x * blockDim.x + threadIdx.x; i < tot;
         i += gridDim.x * blockDim.x) {
        int n = i / K, k = i - n * K;
        float v = (k < Kb) ? s1 * B1[(size_t)k * Ngm + n]
                           : s2 * B2[(size_t)(k - Kb) * Ngm + n];
        __nv_bfloat16 h = __float2bfloat16(v);
        oh[i] = h;
        ol[i] = __float2bfloat16(v - __bfloat162float(h));
        if (k == 0) ob[n] = s1 * b1[n] + s2 * b2[n];
    }
}

// ---------------- warp-MMA split-bf16 GEMM (legacy HMMA path) ----------------
__device__ __forceinline__ uint32_t s2u(const void* p) {
    uint32_t a;
    asm("{ .reg .u64 t; cvta.to.shared.u64 t, %1; cvt.u32.u64 %0, t; }"
        : "=r"(a) : "l"(p));
    return a;
}
__device__ __forceinline__ void ldsm4(uint32_t* r, uint32_t addr) {
    asm volatile("ldmatrix.sync.aligned.m8n8.x4.shared.b16 {%0,%1,%2,%3}, [%4];"
                 : "=r"(r[0]), "=r"(r[1]), "=r"(r[2]), "=r"(r[3]) : "r"(addr));
}
__device__ __forceinline__ void mma16816(float* c, const uint32_t* a, const uint32_t* b) {
    asm volatile(
        "mma.sync.aligned.m16n8k16.row.col.f32.bf16.bf16.f32 "
        "{%0,%1,%2,%3}, {%4,%5,%6,%7}, {%8,%9}, {%0,%1,%2,%3};"
        : "+f"(c[0]), "+f"(c[1]), "+f"(c[2]), "+f"(c[3])
        : "r"(a[0]), "r"(a[1]), "r"(a[2]), "r"(a[3]), "r"(b[0]), "r"(b[1]));
}
__device__ __forceinline__ uint32_t pk2(float a, float b) {
    __nv_bfloat162 h = __floats2bfloat162_rn(a, b);
    return *reinterpret_cast<uint32_t*>(&h);
}

__global__ __launch_bounds__(256, 2) void k_mma_gemm(
    const float* __restrict__ A, int lda, int M, int K,
    const __nv_bfloat16* __restrict__ Bh, const __nv_bfloat16* __restrict__ Bl,
    const float* __restrict__ biasc,
    float* __restrict__ C, int ldc, int relu) {
    __shared__ __nv_bfloat16 sAh[128 * PITCH], sAl[128 * PITCH];
    __shared__ __nv_bfloat16 sBh[128 * PITCH], sBl[128 * PITCH];
    const int t = threadIdx.x, lane = t & 31, wid = t >> 5;
    const int rowBase = blockIdx.y * 128;
    const int n0g = blockIdx.x * 128;
    const int wm = (wid >> 1) * 32, wn = (wid & 1) * 64;
    const uint32_t uAh = s2u(sAh), uAl = s2u(sAl);
    const uint32_t uBh = s2u(sBh), uBl = s2u(sBl);

    float acc[2][8][4];
#pragma unroll
    for (int i = 0; i < 2; i++)
#pragma unroll
        for (int j = 0; j < 8; j++)
#pragma unroll
            for (int q = 0; q < 4; q++) acc[i][j][q] = 0.f;

    const int li = lane & 7;
    const int a_row = (lane >> 3 & 1) * 8 + li;
    const int a_kof = (lane >> 4) * 8;
    // B x4 lane mapping: lanes 0-7 (nt even,k0), 8-15 (nt even,k8),
    //                    16-23 (nt odd,k0), 24-31 (nt odd,k8)
    const int b_nsel = lane >> 4;
    const int b_kof = ((lane >> 3) & 1) * 8;
    const int arow = t >> 1, acol = (t & 1) * 16;

    for (int k0 = 0; k0 < K; k0 += 32) {
        {
            const int gr = rowBase + arow;
            float f[16];
            if (gr < M) {
                const float* ap = A + (size_t)gr * lda + k0 + acol;
#pragma unroll
                for (int q = 0; q < 4; q++) {
                    float4 v = __ldg(reinterpret_cast<const float4*>(ap + q * 4));
                    f[4 * q] = v.x; f[4 * q + 1] = v.y;
                    f[4 * q + 2] = v.z; f[4 * q + 3] = v.w;
                }
            } else {
#pragma unroll
                for (int q = 0; q < 16; q++) f[q] = 0.f;
            }
            uint32_t h[8], l[8];
#pragma unroll
            for (int q = 0; q < 8; q++) {
                float x0 = f[2 * q], x1 = f[2 * q + 1];
                float r0 = x0 - __bfloat162float(__float2bfloat16(x0));
                float r1 = x1 - __bfloat162float(__float2bfloat16(x1));
                h[q] = pk2(x0, x1);
                l[q] = pk2(r0, r1);
            }
            __nv_bfloat16* dh = sAh + arow * PITCH + acol;
            __nv_bfloat16* dl = sAl + arow * PITCH + acol;
            reinterpret_cast<uint4*>(dh)[0] = make_uint4(h[0], h[1], h[2], h[3]);
            reinterpret_cast<uint4*>(dh)[1] = make_uint4(h[4], h[5], h[6], h[7]);
            reinterpret_cast<uint4*>(dl)[0] = make_uint4(l[0], l[1], l[2], l[3]);
            reinterpret_cast<uint4*>(dl)[1] = make_uint4(l[4], l[5], l[6], l[7]);
        }
        {
            const int brow = t >> 1, bcol = (t & 1) * 16;
            const size_t go = (size_t)(n0g + brow) * K + k0 + bcol;
            const uint4* bhp = reinterpret_cast<const uint4*>(Bh + go);
            const uint4* blp = reinterpret_cast<const uint4*>(Bl + go);
            __nv_bfloat16* dh = sBh + brow * PITCH + bcol;
            __nv_bfloat16* dl = sBl + brow * PITCH + bcol;
            reinterpret_cast<uint4*>(dh)[0] = __ldg(bhp);
            reinterpret_cast<uint4*>(dh)[1] = __ldg(bhp + 1);
            reinterpret_cast<uint4*>(dl)[0] = __ldg(blp);
            reinterpret_cast<uint4*>(dl)[1] = __ldg(blp + 1);
        }
        __syncthreads();

#pragma unroll
        for (int ks = 0; ks < 32; ks += 16) {
            uint32_t ah[2][4], al[2][4];
#pragma unroll
            for (int mt = 0; mt < 2; mt++) {
                uint32_t off = ((wm + mt * 16 + a_row) * PITCH + ks + a_kof) * 2;
                ldsm4(ah[mt], uAh + off);
                ldsm4(al[mt], uAl + off);
            }
#pragma unroll
            for (int np = 0; np < 4; np++) {   // nt pairs
                uint32_t bh[4], bl[4];
                uint32_t off =
                    ((wn + (np * 2 + b_nsel) * 8 + li) * PITCH + ks + b_kof) * 2;
                ldsm4(bh, uBh + off);
                ldsm4(bl, uBl + off);
#pragma unroll
                for (int mt = 0; mt < 2; mt++) {
                    mma16816(acc[mt][2 * np], ah[mt], bh);
                    mma16816(acc[mt][2 * np], ah[mt], bl);
                    mma16816(acc[mt][2 * np], al[mt], bh);
                    mma16816(acc[mt][2 * np + 1], ah[mt], bh + 2);
                    mma16816(acc[mt][2 * np + 1], ah[mt], bl + 2);
                    mma16816(acc[mt][2 * np + 1], al[mt], bh + 2);
                }
            }
        }
        __syncthreads();
    }

    const int r4 = lane >> 2, c2 = (lane & 3) * 2;
#pragma unroll
    for (int mt = 0; mt < 2; mt++) {
        const int row0 = rowBase + wm + mt * 16 + r4;
        const int row1 = row0 + 8;
#pragma unroll
        for (int nt = 0; nt < 8; nt++) {
            const int col = n0g + wn + nt * 8 + c2;
            float b0 = __ldg(biasc + col), b1 = __ldg(biasc + col + 1);
            float v0 = acc[mt][nt][0] + b0, v1 = acc[mt][nt][1] + b1;
            float v2 = acc[mt][nt][2] + b0, v3 = acc[mt][nt][3] + b1;
            if (relu) {
                v0 = fmaxf(v0, 0.f); v1 = fmaxf(v1, 0.f);
                v2 = fmaxf(v2, 0.f); v3 = fmaxf(v3, 0.f);
            }
            if (row0 < M)
                *reinterpret_cast<float2*>(C + (size_t)row0 * ldc + col) =
                    make_float2(v0, v1);
            if (row1 < M)
                *reinterpret_cast<float2*>(C + (size_t)row1 * ldc + col) =
                    make_float2(v2, v3);
        }
    }
}

// ---------------- BatchNorm ----------------
// merged: blockIdx.y = node type (0 -> X0/stats[0:], 1 -> X1/stats[256:])
__global__ void k_bn_stats2(const float* __restrict__ X0, const float* __restrict__ X1,
                            float* __restrict__ stats) {
    const float* X = blockIdx.y ? X1 : X0;
    float* st = stats + blockIdx.y * 256;
    const int col = threadIdx.x & 127;
    const int rp = threadIdx.x >> 7;
    float s = 0.f, q = 0.f;
    for (int r = blockIdx.x * 2 + rp; r < N_NODE; r += gridDim.x * 2) {
        float v = X[(size_t)r * EMB + col];
        s += v; q += v * v;
    }
    atomicAdd(&st[col], s);
    atomicAdd(&st[EMB + col], q);
}

__global__ void k_bn_finalize(float* __restrict__ stats, const float* __restrict__ gamma,
                              const float* __restrict__ beta, int layer, float invM) {
    int c = threadIdx.x;
    int type = c >> 7, col = c & 127;
    float mu = stats[type * 256 + col] * invM;
    float var = stats[type * 256 + 128 + col] * invM - mu * mu;
    float a = gamma[layer * EMB + col] * rsqrtf(var + 1e-5f);
    float b = beta[layer * EMB + col] - a * mu;
    stats[512 + type * 256 + col] = a;
    stats[512 + type * 256 + 128 + col] = b;
}

__global__ void k_bn_apply2(const float* __restrict__ X0, float* __restrict__ Y0,
                            const float* __restrict__ X1, float* __restrict__ Y1,
                            const float* __restrict__ stats, int relu) {
    const int n = N_NODE * EMB;
    for (int i = blockIdx.x * blockDim.x + threadIdx.x; i < 2 * n;
         i += gridDim.x * blockDim.x) {
        int col = i & 127;
        if (i < n) {
            float v = stats[512 + col] * X0[i] + stats[512 + 128 + col];
            if (relu) v = fmaxf(v, 0.f);
            Y0[i] = v;
        } else {
            int j = i - n;
            float v = stats[768 + col] * X1[j] + stats[768 + 128 + col];
            if (relu) v = fmaxf(v, 0.f);
            Y1[j] = v;
        }
    }
}

// ---------------- host orchestration ----------------
extern "C" void kernel_launch(void* const* d_in, const int* in_sizes, int n_in,
                              void* d_out, int out_size) {
    (void)in_sizes; (void)n_in; (void)out_size;
    const float* x0   = (const float*)d_in[0];
    const float* x1   = (const float*)d_in[1];
    const float* ea11 = (const float*)d_in[2];
    const float* ea10 = (const float*)d_in[3];
    const float* ea01 = (const float*)d_in[4];
    const float* ea00 = (const float*)d_in[5];
    const int*   ei11 = (const int*)d_in[6];
    const int*   ei10 = (const int*)d_in[7];
    const int*   ei01 = (const int*)d_in[8];
    const int*   ei00 = (const int*)d_in[9];
    const float* Wx  = (const float*)d_in[10];
    const float* bx  = (const float*)d_in[11];
    const float* We  = (const float*)d_in[12];
    const float* be  = (const float*)d_in[13];
    const float* gW1 = (const float*)d_in[14];
    const float* gb1 = (const float*)d_in[15];
    const float* gW2 = (const float*)d_in[16];
    const float* gb2 = (const float*)d_in[17];
    const float* W10 = (const float*)d_in[18];
    const float* b10 = (const float*)d_in[19];
    const float* W01 = (const float*)d_in[20];
    const float* b01 = (const float*)d_in[21];
    const float* W00 = (const float*)d_in[22];
    const float* b00 = (const float*)d_in[23];
    const float* gamma = (const float*)d_in[24];
    const float* beta  = (const float*)d_in[25];
    float* out = (float*)d_out;

    float *h0, *h1, *n0b, *n1b, *E11, *E01, *E10, *E00, *a11, *cat0, *cat1;
    float *esum, *deg, *stats, *biasc;
    __nv_bfloat16 *bth, *btl;
    cudaGetSymbolAddress((void**)&h0,   g_h0);
    cudaGetSymbolAddress((void**)&h1,   g_h1);
    cudaGetSymbolAddress((void**)&n0b,  g_n0);
    cudaGetSymbolAddress((void**)&n1b,  g_n1);
    cudaGetSymbolAddress((void**)&E11,  g_E11);
    cudaGetSymbolAddress((void**)&E01,  g_E01);
    cudaGetSymbolAddress((void**)&E10,  g_E10);
    cudaGetSymbolAddress((void**)&E00,  g_E00);
    cudaGetSymbolAddress((void**)&a11,  g_a11);
    cudaGetSymbolAddress((void**)&cat0, g_cat0);
    cudaGetSymbolAddress((void**)&cat1, g_cat1);
    cudaGetSymbolAddress((void**)&esum, g_esum);
    cudaGetSymbolAddress((void**)&deg,  g_deg);
    cudaGetSymbolAddress((void**)&stats, g_stats);
    cudaGetSymbolAddress((void**)&bth,  g_bth);
    cudaGetSymbolAddress((void**)&btl,  g_btl);
    cudaGetSymbolAddress((void**)&biasc, g_biasc);

    // ---- weight prep ----
    k_prep<<<128, 256>>>(Wx, Wx, 256, 256, 128, 128, 1.f, 0.f, bx, bx,
                         bth, btl, biasc);
    k_prep<<<128, 256>>>(gW1, gW1, 128, 128, 256, 256, 1.f, 0.f, gb1, gb1,
                         bth + 32768, btl + 32768, biasc + 256);
    k_prep<<<192, 256>>>(gW2, W01, 256, 384, 128, 128, 0.5f, 0.05f, gb2, b01,
                         bth + 65536, btl + 65536, biasc + 512);
    k_prep<<<128, 256>>>(W10, W00, 128, 256, 128, 128, 0.05f, 0.05f, b10, b00,
                         bth + 114688, btl + 114688, biasc + 768);

    // ---- edge phase: merged 16-wide sums + degree, then merged per-node GEMV ----
    k_zero<<<2048, 256>>>(esum, 4 * N_NODE * 4);
    k_zero<<<512, 256>>>(deg, N_NODE);
    {
        dim3 ge(512, 4);
        k_edge_sum4<<<ge, 256>>>(ea11, ei11 + N_EDGE, ea01, ei01 + N_EDGE,
                                 ea10, ei10 + N_EDGE, ea00, ei00 + N_EDGE,
                                 esum, deg);
        dim3 gv(512, 4);
        k_edge_gemm4<<<gv, 256>>>(esum, deg, We, be, E11, E01, E10, E00);
    }

    const int MT = (N_NODE + 127) / 128;   // 782 row tiles
    dim3 gg1(1, MT), gg2(2, MT);

    // Input embeddings: h = x @ Wx + bx
    k_mma_gemm<<<gg1, 256>>>(x0, 256, N_NODE, 256, bth, btl, biasc, h0, 128, 0);
    k_mma_gemm<<<gg1, 256>>>(x1, 256, N_NODE, 256, bth, btl, biasc, h1, 128, 0);

    const int sgrid = (N_EDGE * 32) / 256;  // 1 warp per edge
    float* cur0 = h0;
    float* cur1 = h1;

    for (int layer = 0; layer < 2; layer++) {
        float* o0 = (layer == 0) ? n0b : h0;
        float* o1 = (layer == 0) ? n1b : h1;

        k_init_layer<<<2048, 256>>>(cat0, cat1, a11, E10, E00, E01, E11, cur1);

        // scatters ordered by shared source table: h1-readers, then h0-readers
        k_scatter<<<sgrid, 256>>>(cur1, ei11, ei11 + N_EDGE, a11, 128, 0);
        k_scatter<<<sgrid, 256>>>(cur1, ei10, ei10 + N_EDGE, cat0, 256, 0);
        k_scatter<<<sgrid, 256>>>(cur0, ei01, ei01 + N_EDGE, cat1, 384, 256);
        k_scatter<<<sgrid, 256>>>(cur0, ei00, ei00 + N_EDGE, cat0, 256, 128);

        // T = relu(a11 @ gW1 + gb1) -> cat1 cols [0,256)
        k_mma_gemm<<<gg2, 256>>>(a11, 128, N_NODE, 128,
                                 bth + 32768, btl + 32768, biasc + 256,
                                 cat1, 384, 1);
        // new1 = [T | a01] @ [0.5*gW2 ; 0.05*W01] + combined bias
        k_mma_gemm<<<gg1, 256>>>(cat1, 384, N_NODE, 384,
                                 bth + 65536, btl + 65536, biasc + 512,
                                 o1, 128, 0);
        // new0 = [a10 | a00] @ [0.05*W10 ; 0.05*W00] + combined bias
        k_mma_gemm<<<gg1, 256>>>(cat0, 256, N_NODE, 256,
                                 bth + 114688, btl + 114688, biasc + 768,
                                 o0, 128, 0);

        // BatchNorm
        k_zero<<<1, 128>>>(stats, 128);
        {
            dim3 gs(1024, 2);
            k_bn_stats2<<<gs, 256>>>(o0, o1, stats);
        }
        k_bn_finalize<<<1, 256>>>(stats, gamma, beta, layer, 1.f / N_NODE);
        int relu = (layer == 0) ? 1 : 0;
        float* dst0 = (layer == 0) ? o0 : out;
        float* dst1 = (layer == 0) ? o1 : out + (size_t)N_NODE * EMB;
        k_bn_apply2<<<2048, 256>>>(o0, dst0, o1, dst1, stats, relu);

        cur0 = o0;
        cur1 = o1;
    }
}

// round 14
// speedup vs baseline: 1.2185x; 1.0071x over previous
#include <cuda_runtime.h>
#include <cuda_bf16.h>
#include <cstdint>

#define N_NODE 100000
#define N_EDGE 800000
#define EMB 128
#define PITCH 40   // bf16 elems per smem row: 32 data + 8 pad = 80 bytes

// ---------------- static device scratch (allocation-free) ----------------
__device__ float g_h0[N_NODE * EMB];
__device__ float g_h1[N_NODE * EMB];
__device__ float g_n0[N_NODE * EMB];
__device__ float g_n1[N_NODE * EMB];
__device__ float g_E11[N_NODE * EMB];
__device__ float g_E01[N_NODE * EMB];
__device__ float g_E10[N_NODE * EMB];
__device__ float g_E00[N_NODE * EMB];
__device__ float g_a11[N_NODE * EMB];
__device__ float g_cat0[N_NODE * 256];   // [agg10 | agg00]
__device__ float g_cat1[N_NODE * 384];   // [T(256) | agg01(128)]
__device__ float g_esum[4 * N_NODE * 16];
__device__ float g_deg[4 * N_NODE];
__device__ float g_stats[1024];
// pre-transposed / pre-split / pre-scaled weights: [N][K] bf16 hi/lo
__device__ __align__(16) __nv_bfloat16 g_bth[147456];
__device__ __align__(16) __nv_bfloat16 g_btl[147456];
__device__ float g_biasc[1024];

// ---------------- tiny utility kernels ----------------
__global__ void k_zero(float* __restrict__ p, int n4) {
    float4 z = make_float4(0.f, 0.f, 0.f, 0.f);
    for (int i = blockIdx.x * blockDim.x + threadIdx.x; i < n4;
         i += gridDim.x * blockDim.x)
        reinterpret_cast<float4*>(p)[i] = z;
}

__device__ __forceinline__ void red_add_v4(float* p, float4 v) {
    asm volatile("red.global.add.v4.f32 [%0], {%1,%2,%3,%4};"
                 :: "l"(p), "f"(v.x), "f"(v.y), "f"(v.z), "f"(v.w)
                 : "memory");
}
__device__ __forceinline__ void red_add_f32(float* p, float v) {
    asm volatile("red.global.add.f32 [%0], %1;" :: "l"(p), "f"(v) : "memory");
}

// ---------------- merged edge phase ----------------
__global__ void k_edge_sum4(const float* __restrict__ ea0, const int* __restrict__ d0,
                            const float* __restrict__ ea1, const int* __restrict__ d1,
                            const float* __restrict__ ea2, const int* __restrict__ d2,
                            const float* __restrict__ ea3, const int* __restrict__ d3,
                            float* __restrict__ esum, float* __restrict__ deg) {
    const int ty = blockIdx.y;
    const float* ea = (ty == 0) ? ea0 : (ty == 1) ? ea1 : (ty == 2) ? ea2 : ea3;
    const int* dst  = (ty == 0) ? d0  : (ty == 1) ? d1  : (ty == 2) ? d2  : d3;
    float* Esum = esum + (size_t)ty * N_NODE * 16;
    float* dg   = deg + (size_t)ty * N_NODE;
    const int n = N_EDGE * 4;
    for (int i = blockIdx.x * blockDim.x + threadIdx.x; i < n;
         i += gridDim.x * blockDim.x) {
        int e = i >> 2, q = i & 3;
        int d = __ldg(&dst[e]);
        float4 v = *reinterpret_cast<const float4*>(ea + (size_t)e * 16 + q * 4);
        red_add_v4(Esum + (size_t)d * 16 + q * 4, v);
        if (q == 0) red_add_f32(dg + d, 1.0f);
    }
}

__global__ void k_edge_gemm4(const float* __restrict__ esum, const float* __restrict__ deg,
                             const float* __restrict__ We, const float* __restrict__ be,
                             float* __restrict__ E0, float* __restrict__ E1,
                             float* __restrict__ E2, float* __restrict__ E3) {
    __shared__ float sW[16 * EMB];
    for (int i = threadIdx.x; i < 16 * EMB; i += blockDim.x) sW[i] = We[i];
    __syncthreads();
    const int ty = blockIdx.y;
    const float* Esum = esum + (size_t)ty * N_NODE * 16;
    const float* dgp  = deg + (size_t)ty * N_NODE;
    float* Eout = (ty == 0) ? E0 : (ty == 1) ? E1 : (ty == 2) ? E2 : E3;
    const int lane = threadIdx.x & 31;
    const int warp = (blockIdx.x * blockDim.x + threadIdx.x) >> 5;
    const int nwarp = (gridDim.x * blockDim.x) >> 5;
    const int c0 = lane * 4;
    const float4 bev = *reinterpret_cast<const float4*>(be + c0);
    for (int r = warp; r < N_NODE; r += nwarp) {
        float av = (lane < 16) ? Esum[(size_t)r * 16 + lane] : 0.f;
        float dg = __ldg(&dgp[r]);
        float4 acc = make_float4(dg * bev.x, dg * bev.y, dg * bev.z, dg * bev.w);
#pragma unroll
        for (int k = 0; k < 16; k++) {
            float a = __shfl_sync(0xffffffffu, av, k);
            float4 w = *reinterpret_cast<const float4*>(sW + k * EMB + c0);
            acc.x += a * w.x; acc.y += a * w.y; acc.z += a * w.z; acc.w += a * w.w;
        }
        *reinterpret_cast<float4*>(Eout + (size_t)r * EMB + c0) = acc;
    }
}

// ---------------- merged scatter: 2 jobs sharing one source table ----------------
// job = blockIdx.y; agg[dst*ldc+off] += f(h[src]); f = BN-affine+relu when coef
__global__ void k_scatter2(const float* __restrict__ h,
                           const int* __restrict__ s0, const int* __restrict__ d0,
                           float* __restrict__ a0, int l0, int o0,
                           const int* __restrict__ s1, const int* __restrict__ d1,
                           float* __restrict__ a1, int l1, int o1,
                           const float* __restrict__ coef) {
    const int lane = threadIdx.x & 31;
    const int warp = (blockIdx.x * blockDim.x + threadIdx.x) >> 5;
    if (warp >= N_EDGE) return;
    const int jb = blockIdx.y;
    const int* src = jb ? s1 : s0;
    const int* dst = jb ? d1 : d0;
    float* agg = jb ? a1 : a0;
    const int ldc = jb ? l1 : l0;
    const int off = jb ? o1 : o0;
    int s = __ldg(&src[warp]);
    int d = __ldg(&dst[warp]);
    const int c0 = lane * 4;
    float4 v = *reinterpret_cast<const float4*>(h + (size_t)s * EMB + c0);
    if (coef) {
        float4 ca = *reinterpret_cast<const float4*>(coef + c0);
        float4 cb = *reinterpret_cast<const float4*>(coef + 128 + c0);
        v.x = fmaxf(ca.x * v.x + cb.x, 0.f);
        v.y = fmaxf(ca.y * v.y + cb.y, 0.f);
        v.z = fmaxf(ca.z * v.z + cb.z, 0.f);
        v.w = fmaxf(ca.w * v.w + cb.w, 0.f);
    }
    red_add_v4(agg + (size_t)d * ldc + off + c0, v);
}

// ---------------- fused per-layer init (+ optional BN on h1 self-term) ----------------
__global__ void k_init_layer(float* __restrict__ cat0, float* __restrict__ cat1,
                             float* __restrict__ a11,
                             const float* __restrict__ E10, const float* __restrict__ E00,
                             const float* __restrict__ E01, const float* __restrict__ E11,
                             const float* __restrict__ h1,
                             const float* __restrict__ coef1) {
    const int n = N_NODE * 32;
    for (int i = blockIdx.x * blockDim.x + threadIdx.x; i < n;
         i += gridDim.x * blockDim.x) {
        int r = i >> 5, c = i & 31;
        reinterpret_cast<float4*>(cat0)[r * 64 + c] =
            reinterpret_cast<const float4*>(E10)[i];
        reinterpret_cast<float4*>(cat0)[r * 64 + 32 + c] =
            reinterpret_cast<const float4*>(E00)[i];
        reinterpret_cast<float4*>(cat1)[r * 96 + 64 + c] =
            reinterpret_cast<const float4*>(E01)[i];
        float4 ev = reinterpret_cast<const float4*>(E11)[i];
        float4 hv = reinterpret_cast<const float4*>(h1)[i];
        if (coef1) {
            const int c0 = c * 4;
            float4 ca = *reinterpret_cast<const float4*>(coef1 + c0);
            float4 cb = *reinterpret_cast<const float4*>(coef1 + 128 + c0);
            hv.x = fmaxf(ca.x * hv.x + cb.x, 0.f);
            hv.y = fmaxf(ca.y * hv.y + cb.y, 0.f);
            hv.z = fmaxf(ca.z * hv.z + cb.z, 0.f);
            hv.w = fmaxf(ca.w * hv.w + cb.w, 0.f);
        }
        ev.x += 1.1f * hv.x; ev.y += 1.1f * hv.y;
        ev.z += 1.1f * hv.z; ev.w += 1.1f * hv.w;
        reinterpret_cast<float4*>(a11)[i] = ev;
    }
}

// ---------------- weight prep ----------------
__global__ void k_prep(const float* __restrict__ B1, const float* __restrict__ B2,
                       int Kb, int K, int Ngm, int Nout, float s1, float s2,
                       const float* __restrict__ b1, const float* __restrict__ b2,
                       __nv_bfloat16* __restrict__ oh, __nv_bfloat16* __restrict__ ol,
                       float* __restrict__ ob) {
    const int tot = Nout * K;
    for (int i = blockIdx.x * blockDim.x + threadIdx.x; i < tot;
         i += gridDim.x * blockDim.x) {
        int n = i / K, k = i - n * K;
        float v = (k < Kb) ? s1 * B1[(size_t)k * Ngm + n]
                           : s2 * B2[(size_t)(k - Kb) * Ngm + n];
        __nv_bfloat16 h = __float2bfloat16(v);
        oh[i] = h;
        ol[i] = __float2bfloat16(v - __bfloat162float(h));
        if (k == 0) ob[n] = s1 * b1[n] + s2 * b2[n];
    }
}

// ---------------- warp-MMA split-bf16 GEMM (legacy HMMA path), dual-job ----------------
__device__ __forceinline__ uint32_t s2u(const void* p) {
    uint32_t a;
    asm("{ .reg .u64 t; cvta.to.shared.u64 t, %1; cvt.u32.u64 %0, t; }"
        : "=r"(a) : "l"(p));
    return a;
}
__device__ __forceinline__ void ldsm4(uint32_t* r, uint32_t addr) {
    asm volatile("ldmatrix.sync.aligned.m8n8.x4.shared.b16 {%0,%1,%2,%3}, [%4];"
                 : "=r"(r[0]), "=r"(r[1]), "=r"(r[2]), "=r"(r[3]) : "r"(addr));
}
__device__ __forceinline__ void mma16816(float* c, const uint32_t* a, const uint32_t* b) {
    asm volatile(
        "mma.sync.aligned.m16n8k16.row.col.f32.bf16.bf16.f32 "
        "{%0,%1,%2,%3}, {%4,%5,%6,%7}, {%8,%9}, {%0,%1,%2,%3};"
        : "+f"(c[0]), "+f"(c[1]), "+f"(c[2]), "+f"(c[3])
        : "r"(a[0]), "r"(a[1]), "r"(a[2]), "r"(a[3]), "r"(b[0]), "r"(b[1]));
}
__device__ __forceinline__ uint32_t pk2(float a, float b) {
    __nv_bfloat162 h = __floats2bfloat162_rn(a, b);
    return *reinterpret_cast<uint32_t*>(&h);
}

struct GJob {
    const float* A; int lda, K;
    const __nv_bfloat16* Bh; const __nv_bfloat16* Bl;
    const float* biasc;
    float* C; int ldc, relu, nx;
};

__global__ __launch_bounds__(256, 2) void k_mma_gemm(GJob j0, GJob j1) {
    const GJob& j = blockIdx.z ? j1 : j0;
    if ((int)blockIdx.x >= j.nx) return;
    const float* __restrict__ A = j.A;
    const __nv_bfloat16* __restrict__ Bh = j.Bh;
    const __nv_bfloat16* __restrict__ Bl = j.Bl;
    const int lda = j.lda, K = j.K, ldc = j.ldc, relu = j.relu;
    const int M = N_NODE;

    __shared__ __nv_bfloat16 sAh[128 * PITCH], sAl[128 * PITCH];
    __shared__ __nv_bfloat16 sBh[128 * PITCH], sBl[128 * PITCH];
    const int t = threadIdx.x, lane = t & 31, wid = t >> 5;
    const int rowBase = blockIdx.y * 128;
    const int n0g = blockIdx.x * 128;
    const int wm = (wid >> 1) * 32, wn = (wid & 1) * 64;
    const uint32_t uAh = s2u(sAh), uAl = s2u(sAl);
    const uint32_t uBh = s2u(sBh), uBl = s2u(sBl);

    float acc[2][8][4];
#pragma unroll
    for (int i = 0; i < 2; i++)
#pragma unroll
        for (int jj = 0; jj < 8; jj++)
#pragma unroll
            for (int q = 0; q < 4; q++) acc[i][jj][q] = 0.f;

    const int li = lane & 7;
    const int a_row = (lane >> 3 & 1) * 8 + li;
    const int a_kof = (lane >> 4) * 8;
    const int b_nsel = lane >> 4;
    const int b_kof = ((lane >> 3) & 1) * 8;
    const int arow = t >> 1, acol = (t & 1) * 16;

    for (int k0 = 0; k0 < K; k0 += 32) {
        {
            const int gr = rowBase + arow;
            float f[16];
            if (gr < M) {
                const float* ap = A + (size_t)gr * lda + k0 + acol;
#pragma unroll
                for (int q = 0; q < 4; q++) {
                    float4 v = __ldg(reinterpret_cast<const float4*>(ap + q * 4));
                    f[4 * q] = v.x; f[4 * q + 1] = v.y;
                    f[4 * q + 2] = v.z; f[4 * q + 3] = v.w;
                }
            } else {
#pragma unroll
                for (int q = 0; q < 16; q++) f[q] = 0.f;
            }
            uint32_t h[8], l[8];
#pragma unroll
            for (int q = 0; q < 8; q++) {
                float x0 = f[2 * q], x1 = f[2 * q + 1];
                float r0 = x0 - __bfloat162float(__float2bfloat16(x0));
                float r1 = x1 - __bfloat162float(__float2bfloat16(x1));
                h[q] = pk2(x0, x1);
                l[q] = pk2(r0, r1);
            }
            __nv_bfloat16* dh = sAh + arow * PITCH + acol;
            __nv_bfloat16* dl = sAl + arow * PITCH + acol;
            reinterpret_cast<uint4*>(dh)[0] = make_uint4(h[0], h[1], h[2], h[3]);
            reinterpret_cast<uint4*>(dh)[1] = make_uint4(h[4], h[5], h[6], h[7]);
            reinterpret_cast<uint4*>(dl)[0] = make_uint4(l[0], l[1], l[2], l[3]);
            reinterpret_cast<uint4*>(dl)[1] = make_uint4(l[4], l[5], l[6], l[7]);
        }
        {
            const int brow = t >> 1, bcol = (t & 1) * 16;
            const size_t go = (size_t)(n0g + brow) * K + k0 + bcol;
            const uint4* bhp = reinterpret_cast<const uint4*>(Bh + go);
            const uint4* blp = reinterpret_cast<const uint4*>(Bl + go);
            __nv_bfloat16* dh = sBh + brow * PITCH + bcol;
            __nv_bfloat16* dl = sBl + brow * PITCH + bcol;
            reinterpret_cast<uint4*>(dh)[0] = __ldg(bhp);
            reinterpret_cast<uint4*>(dh)[1] = __ldg(bhp + 1);
            reinterpret_cast<uint4*>(dl)[0] = __ldg(blp);
            reinterpret_cast<uint4*>(dl)[1] = __ldg(blp + 1);
        }
        __syncthreads();

#pragma unroll
        for (int ks = 0; ks < 32; ks += 16) {
            uint32_t ah[2][4], al[2][4];
#pragma unroll
            for (int mt = 0; mt < 2; mt++) {
                uint32_t off = ((wm + mt * 16 + a_row) * PITCH + ks + a_kof) * 2;
                ldsm4(ah[mt], uAh + off);
                ldsm4(al[mt], uAl + off);
            }
#pragma unroll
            for (int np = 0; np < 4; np++) {
                uint32_t bh[4], bl[4];
                uint32_t off =
                    ((wn + (np * 2 + b_nsel) * 8 + li) * PITCH + ks + b_kof) * 2;
                ldsm4(bh, uBh + off);
                ldsm4(bl, uBl + off);
#pragma unroll
                for (int mt = 0; mt < 2; mt++) {
                    mma16816(acc[mt][2 * np], ah[mt], bh);
                    mma16816(acc[mt][2 * np], ah[mt], bl);
                    mma16816(acc[mt][2 * np], al[mt], bh);
                    mma16816(acc[mt][2 * np + 1], ah[mt], bh + 2);
                    mma16816(acc[mt][2 * np + 1], ah[mt], bl + 2);
                    mma16816(acc[mt][2 * np + 1], al[mt], bh + 2);
                }
            }
        }
        __syncthreads();
    }

    const int r4 = lane >> 2, c2 = (lane & 3) * 2;
#pragma unroll
    for (int mt = 0; mt < 2; mt++) {
        const int row0 = rowBase + wm + mt * 16 + r4;
        const int row1 = row0 + 8;
#pragma unroll
        for (int nt = 0; nt < 8; nt++) {
            const int col = n0g + wn + nt * 8 + c2;
            float b0 = __ldg(j.biasc + col), b1 = __ldg(j.biasc + col + 1);
            float v0 = acc[mt][nt][0] + b0, v1 = acc[mt][nt][1] + b1;
            float v2 = acc[mt][nt][2] + b0, v3 = acc[mt][nt][3] + b1;
            if (relu) {
                v0 = fmaxf(v0, 0.f); v1 = fmaxf(v1, 0.f);
                v2 = fmaxf(v2, 0.f); v3 = fmaxf(v3, 0.f);
            }
            if (row0 < M)
                *reinterpret_cast<float2*>(j.C + (size_t)row0 * ldc + col) =
                    make_float2(v0, v1);
            if (row1 < M)
                *reinterpret_cast<float2*>(j.C + (size_t)row1 * ldc + col) =
                    make_float2(v2, v3);
        }
    }
}

// ---------------- BatchNorm ----------------
__global__ void k_bn_stats2(const float* __restrict__ X0, const float* __restrict__ X1,
                            float* __restrict__ stats) {
    const float* X = blockIdx.y ? X1 : X0;
    float* st = stats + blockIdx.y * 256;
    const int col = threadIdx.x & 127;
    const int rp = threadIdx.x >> 7;
    float s = 0.f, q = 0.f;
    for (int r = blockIdx.x * 2 + rp; r < N_NODE; r += gridDim.x * 2) {
        float v = X[(size_t)r * EMB + col];
        s += v; q += v * v;
    }
    atomicAdd(&st[col], s);
    atomicAdd(&st[EMB + col], q);
}

__global__ void k_bn_finalize(float* __restrict__ stats, const float* __restrict__ gamma,
                              const float* __restrict__ beta, int layer, float invM) {
    int c = threadIdx.x;
    int type = c >> 7, col = c & 127;
    float mu = stats[type * 256 + col] * invM;
    float var = stats[type * 256 + 128 + col] * invM - mu * mu;
    float a = gamma[layer * EMB + col] * rsqrtf(var + 1e-5f);
    float b = beta[layer * EMB + col] - a * mu;
    stats[512 + type * 256 + col] = a;
    stats[512 + type * 256 + 128 + col] = b;
}

__global__ void k_bn_apply2(const float* __restrict__ X0, float* __restrict__ Y0,
                            const float* __restrict__ X1, float* __restrict__ Y1,
                            const float* __restrict__ stats, int relu) {
    const int n = N_NODE * EMB;
    for (int i = blockIdx.x * blockDim.x + threadIdx.x; i < 2 * n;
         i += gridDim.x * blockDim.x) {
        int col = i & 127;
        if (i < n) {
            float v = stats[512 + col] * X0[i] + stats[512 + 128 + col];
            if (relu) v = fmaxf(v, 0.f);
            Y0[i] = v;
        } else {
            int j = i - n;
            float v = stats[768 + col] * X1[j] + stats[768 + 128 + col];
            if (relu) v = fmaxf(v, 0.f);
            Y1[j] = v;
        }
    }
}

// ---------------- host orchestration ----------------
extern "C" void kernel_launch(void* const* d_in, const int* in_sizes, int n_in,
                              void* d_out, int out_size) {
    (void)in_sizes; (void)n_in; (void)out_size;
    const float* x0   = (const float*)d_in[0];
    const float* x1   = (const float*)d_in[1];
    const float* ea11 = (const float*)d_in[2];
    const float* ea10 = (const float*)d_in[3];
    const float* ea01 = (const float*)d_in[4];
    const float* ea00 = (const float*)d_in[5];
    const int*   ei11 = (const int*)d_in[6];
    const int*   ei10 = (const int*)d_in[7];
    const int*   ei01 = (const int*)d_in[8];
    const int*   ei00 = (const int*)d_in[9];
    const float* Wx  = (const float*)d_in[10];
    const float* bx  = (const float*)d_in[11];
    const float* We  = (const float*)d_in[12];
    const float* be  = (const float*)d_in[13];
    const float* gW1 = (const float*)d_in[14];
    const float* gb1 = (const float*)d_in[15];
    const float* gW2 = (const float*)d_in[16];
    const float* gb2 = (const float*)d_in[17];
    const float* W10 = (const float*)d_in[18];
    const float* b10 = (const float*)d_in[19];
    const float* W01 = (const float*)d_in[20];
    const float* b01 = (const float*)d_in[21];
    const float* W00 = (const float*)d_in[22];
    const float* b00 = (const float*)d_in[23];
    const float* gamma = (const float*)d_in[24];
    const float* beta  = (const float*)d_in[25];
    float* out = (float*)d_out;

    float *h0, *h1, *n0b, *n1b, *E11, *E01, *E10, *E00, *a11, *cat0, *cat1;
    float *esum, *deg, *stats, *biasc;
    __nv_bfloat16 *bth, *btl;
    cudaGetSymbolAddress((void**)&h0,   g_h0);
    cudaGetSymbolAddress((void**)&h1,   g_h1);
    cudaGetSymbolAddress((void**)&n0b,  g_n0);
    cudaGetSymbolAddress((void**)&n1b,  g_n1);
    cudaGetSymbolAddress((void**)&E11,  g_E11);
    cudaGetSymbolAddress((void**)&E01,  g_E01);
    cudaGetSymbolAddress((void**)&E10,  g_E10);
    cudaGetSymbolAddress((void**)&E00,  g_E00);
    cudaGetSymbolAddress((void**)&a11,  g_a11);
    cudaGetSymbolAddress((void**)&cat0, g_cat0);
    cudaGetSymbolAddress((void**)&cat1, g_cat1);
    cudaGetSymbolAddress((void**)&esum, g_esum);
    cudaGetSymbolAddress((void**)&deg,  g_deg);
    cudaGetSymbolAddress((void**)&stats, g_stats);
    cudaGetSymbolAddress((void**)&bth,  g_bth);
    cudaGetSymbolAddress((void**)&btl,  g_btl);
    cudaGetSymbolAddress((void**)&biasc, g_biasc);

    // ---- weight prep ----
    k_prep<<<128, 256>>>(Wx, Wx, 256, 256, 128, 128, 1.f, 0.f, bx, bx,
                         bth, btl, biasc);
    k_prep<<<128, 256>>>(gW1, gW1, 128, 128, 256, 256, 1.f, 0.f, gb1, gb1,
                         bth + 32768, btl + 32768, biasc + 256);
    k_prep<<<192, 256>>>(gW2, W01, 256, 384, 128, 128, 0.5f, 0.05f, gb2, b01,
                         bth + 65536, btl + 65536, biasc + 512);
    k_prep<<<128, 256>>>(W10, W00, 128, 256, 128, 128, 0.05f, 0.05f, b10, b00,
                         bth + 114688, btl + 114688, biasc + 768);

    // ---- edge phase ----
    k_zero<<<2048, 256>>>(esum, 4 * N_NODE * 4);
    k_zero<<<512, 256>>>(deg, N_NODE);
    {
        dim3 ge(512, 4);
        k_edge_sum4<<<ge, 256>>>(ea11, ei11 + N_EDGE, ea01, ei01 + N_EDGE,
                                 ea10, ei10 + N_EDGE, ea00, ei00 + N_EDGE,
                                 esum, deg);
        dim3 gv(512, 4);
        k_edge_gemm4<<<gv, 256>>>(esum, deg, We, be, E11, E01, E10, E00);
    }

    const int MT = (N_NODE + 127) / 128;   // 782 row tiles

    // GEMM job configs
    GJob jX0 = {x0, 256, 256, bth, btl, biasc, h0, 128, 0, 1};
    GJob jX1 = {x1, 256, 256, bth, btl, biasc, h1, 128, 0, 1};
    GJob jT  = {a11, 128, 128, bth + 32768, btl + 32768, biasc + 256,
                cat1, 384, 1, 2};
    GJob jN1 = {cat1, 384, 384, bth + 65536, btl + 65536, biasc + 512,
                nullptr, 128, 0, 1};
    GJob jN0 = {cat0, 256, 256, bth + 114688, btl + 114688, biasc + 768,
                nullptr, 128, 0, 1};

    // Input embeddings (merged pair)
    {
        dim3 g(1, MT, 2);
        k_mma_gemm<<<g, 256>>>(jX0, jX1);
    }

    const int sgrid = (N_EDGE * 32) / 256;  // 1 warp per edge
    float* cur0 = h0;
    float* cur1 = h1;

    for (int layer = 0; layer < 2; layer++) {
        float* o0 = (layer == 0) ? n0b : h0;
        float* o1 = (layer == 0) ? n1b : h1;
        const float* c0p = (layer == 0) ? nullptr : stats + 512;
        const float* c1p = (layer == 0) ? nullptr : stats + 768;

        k_init_layer<<<2048, 256>>>(cat0, cat1, a11, E10, E00, E01, E11, cur1, c1p);

        // merged scatters: h1-sourced pair, then h0-sourced pair
        {
            dim3 gs(sgrid, 2);
            k_scatter2<<<gs, 256>>>(cur1,
                                    ei11, ei11 + N_EDGE, a11, 128, 0,
                                    ei10, ei10 + N_EDGE, cat0, 256, 0, c1p);
            k_scatter2<<<gs, 256>>>(cur0,
                                    ei01, ei01 + N_EDGE, cat1, 384, 256,
                                    ei00, ei00 + N_EDGE, cat0, 256, 128, c0p);
        }

        // merged GEMMs: T (nx=2) + new0 (nx=1); then new1
        jN0.C = o0;
        jN1.C = o1;
        {
            dim3 g(2, MT, 2);
            k_mma_gemm<<<g, 256>>>(jT, jN0);
        }
        {
            dim3 g(1, MT, 1);
            k_mma_gemm<<<g, 256>>>(jN1, jN1);
        }

        // BatchNorm stats + finalize (coef region [512,1024) written by finalize)
        k_zero<<<1, 128>>>(stats, 128);
        {
            dim3 gs(1024, 2);
            k_bn_stats2<<<gs, 256>>>(o0, o1, stats);
        }
        k_bn_finalize<<<1, 256>>>(stats, gamma, beta, layer, 1.f / N_NODE);

        // layer 0: BN apply fused into layer-1 consumers; layer 1: final apply
        if (layer == 1)
            k_bn_apply2<<<2048, 256>>>(h0, out, h1, out + (size_t)N_NODE * EMB,
                                       stats, 0);

        cur0 = o0;
        cur1 = o1;
    }
}

// round 15
// speedup vs baseline: 1.2744x; 1.0459x over previous
#include <cuda_runtime.h>
#include <cuda_bf16.h>
#include <cstdint>

#define N_NODE 100000
#define N_EDGE 800000
#define EMB 128
#define PITCH 40   // bf16 elems per smem row: 32 data + 8 pad = 80 bytes

// ---------------- static device scratch (allocation-free) ----------------
__device__ float g_h0[N_NODE * EMB];
__device__ float g_h1[N_NODE * EMB];
__device__ float g_n0[N_NODE * EMB];
__device__ float g_n1[N_NODE * EMB];
__device__ float g_a11[N_NODE * EMB];
__device__ float g_cat0[N_NODE * 256];   // [agg10 | agg00]
__device__ float g_cat1[N_NODE * 384];   // [T(256) | agg01(128)]
__device__ float g_esum[4 * N_NODE * 16];
__device__ float g_deg[4 * N_NODE];
__device__ float g_stats[1024];
// pre-transposed / pre-split / pre-scaled weights: [N][K] bf16 hi/lo
__device__ __align__(16) __nv_bfloat16 g_bth[147456];
__device__ __align__(16) __nv_bfloat16 g_btl[147456];
__device__ float g_biasc[1024];

// ---------------- tiny utility kernels ----------------
__global__ void k_zero(float* __restrict__ p, int n4) {
    float4 z = make_float4(0.f, 0.f, 0.f, 0.f);
    for (int i = blockIdx.x * blockDim.x + threadIdx.x; i < n4;
         i += gridDim.x * blockDim.x)
        reinterpret_cast<float4*>(p)[i] = z;
}

__device__ __forceinline__ void red_add_v4(float* p, float4 v) {
    asm volatile("red.global.add.v4.f32 [%0], {%1,%2,%3,%4};"
                 :: "l"(p), "f"(v.x), "f"(v.y), "f"(v.z), "f"(v.w)
                 : "memory");
}
__device__ __forceinline__ void red_add_f32(float* p, float v) {
    asm volatile("red.global.add.f32 [%0], %1;" :: "l"(p), "f"(v) : "memory");
}

// ---------------- merged edge phase: 16-wide ea sums + degree ----------------
__global__ void k_edge_sum4(const float* __restrict__ ea0, const int* __restrict__ d0,
                            const float* __restrict__ ea1, const int* __restrict__ d1,
                            const float* __restrict__ ea2, const int* __restrict__ d2,
                            const float* __restrict__ ea3, const int* __restrict__ d3,
                            float* __restrict__ esum, float* __restrict__ deg) {
    const int ty = blockIdx.y;
    const float* ea = (ty == 0) ? ea0 : (ty == 1) ? ea1 : (ty == 2) ? ea2 : ea3;
    const int* dst  = (ty == 0) ? d0  : (ty == 1) ? d1  : (ty == 2) ? d2  : d3;
    float* Esum = esum + (size_t)ty * N_NODE * 16;
    float* dg   = deg + (size_t)ty * N_NODE;
    const int n = N_EDGE * 4;
    for (int i = blockIdx.x * blockDim.x + threadIdx.x; i < n;
         i += gridDim.x * blockDim.x) {
        int e = i >> 2, q = i & 3;
        int d = __ldg(&dst[e]);
        float4 v = *reinterpret_cast<const float4*>(ea + (size_t)e * 16 + q * 4);
        red_add_v4(Esum + (size_t)d * 16 + q * 4, v);
        if (q == 0) red_add_f32(dg + d, 1.0f);
    }
}

// ---------------- fused per-layer init + 4-type edge GEMV ----------------
// Per node row r (one warp): Ety[r] = esum_ty[r] @ We + deg_ty[r]*be for 4 types,
// then cat0[r] <- [E10|E00], cat1[r][256:] <- E01, a11[r] <- E11 + 1.1*f(h1[r]).
// esum type order: 0=11, 1=01, 2=10, 3=00. f = BN-affine+relu when coef1.
__global__ __launch_bounds__(256) void k_init_gemv(
    const float* __restrict__ esum, const float* __restrict__ deg,
    const float* __restrict__ We, const float* __restrict__ be,
    float* __restrict__ cat0, float* __restrict__ cat1, float* __restrict__ a11,
    const float* __restrict__ h1, const float* __restrict__ coef1) {
    __shared__ float sW[16 * EMB];
    for (int i = threadIdx.x; i < 16 * EMB; i += blockDim.x) sW[i] = We[i];
    __syncthreads();
    const int lane = threadIdx.x & 31;
    const int warp = (blockIdx.x * blockDim.x + threadIdx.x) >> 5;
    const int nwarp = (gridDim.x * blockDim.x) >> 5;
    const int c0 = lane * 4;
    const float4 bev = *reinterpret_cast<const float4*>(be + c0);
    for (int r = warp; r < N_NODE; r += nwarp) {
        float a0 = 0.f, a1 = 0.f, a2 = 0.f, a3 = 0.f;
        if (lane < 16) {
            a0 = __ldg(&esum[(size_t)0 * N_NODE * 16 + (size_t)r * 16 + lane]);
            a1 = __ldg(&esum[(size_t)1 * N_NODE * 16 + (size_t)r * 16 + lane]);
            a2 = __ldg(&esum[(size_t)2 * N_NODE * 16 + (size_t)r * 16 + lane]);
            a3 = __ldg(&esum[(size_t)3 * N_NODE * 16 + (size_t)r * 16 + lane]);
        }
        float d0 = __ldg(&deg[0 * N_NODE + r]);
        float d1 = __ldg(&deg[1 * N_NODE + r]);
        float d2 = __ldg(&deg[2 * N_NODE + r]);
        float d3 = __ldg(&deg[3 * N_NODE + r]);
        float4 e0 = make_float4(d0 * bev.x, d0 * bev.y, d0 * bev.z, d0 * bev.w);
        float4 e1 = make_float4(d1 * bev.x, d1 * bev.y, d1 * bev.z, d1 * bev.w);
        float4 e2 = make_float4(d2 * bev.x, d2 * bev.y, d2 * bev.z, d2 * bev.w);
        float4 e3 = make_float4(d3 * bev.x, d3 * bev.y, d3 * bev.z, d3 * bev.w);
#pragma unroll
        for (int k = 0; k < 16; k++) {
            float4 w = *reinterpret_cast<const float4*>(sW + k * EMB + c0);
            float s0 = __shfl_sync(0xffffffffu, a0, k);
            float s1 = __shfl_sync(0xffffffffu, a1, k);
            float s2 = __shfl_sync(0xffffffffu, a2, k);
            float s3 = __shfl_sync(0xffffffffu, a3, k);
            e0.x += s0 * w.x; e0.y += s0 * w.y; e0.z += s0 * w.z; e0.w += s0 * w.w;
            e1.x += s1 * w.x; e1.y += s1 * w.y; e1.z += s1 * w.z; e1.w += s1 * w.w;
            e2.x += s2 * w.x; e2.y += s2 * w.y; e2.z += s2 * w.z; e2.w += s2 * w.w;
            e3.x += s3 * w.x; e3.y += s3 * w.y; e3.z += s3 * w.z; e3.w += s3 * w.w;
        }
        // h1 self-term for GIN (type 11 = e0)
        float4 hv = *reinterpret_cast<const float4*>(h1 + (size_t)r * EMB + c0);
        if (coef1) {
            float4 ca = *reinterpret_cast<const float4*>(coef1 + c0);
            float4 cb = *reinterpret_cast<const float4*>(coef1 + 128 + c0);
            hv.x = fmaxf(ca.x * hv.x + cb.x, 0.f);
            hv.y = fmaxf(ca.y * hv.y + cb.y, 0.f);
            hv.z = fmaxf(ca.z * hv.z + cb.z, 0.f);
            hv.w = fmaxf(ca.w * hv.w + cb.w, 0.f);
        }
        e0.x += 1.1f * hv.x; e0.y += 1.1f * hv.y;
        e0.z += 1.1f * hv.z; e0.w += 1.1f * hv.w;
        *reinterpret_cast<float4*>(a11 + (size_t)r * EMB + c0) = e0;
        *reinterpret_cast<float4*>(cat1 + (size_t)r * 384 + 256 + c0) = e1;
        *reinterpret_cast<float4*>(cat0 + (size_t)r * 256 + c0) = e2;
        *reinterpret_cast<float4*>(cat0 + (size_t)r * 256 + 128 + c0) = e3;
    }
}

// ---------------- merged scatter: 2 jobs sharing one source table ----------------
__global__ void k_scatter2(const float* __restrict__ h,
                           const int* __restrict__ s0, const int* __restrict__ d0,
                           float* __restrict__ a0, int l0, int o0,
                           const int* __restrict__ s1, const int* __restrict__ d1,
                           float* __restrict__ a1, int l1, int o1,
                           const float* __restrict__ coef) {
    const int lane = threadIdx.x & 31;
    const int warp = (blockIdx.x * blockDim.x + threadIdx.x) >> 5;
    if (warp >= N_EDGE) return;
    const int jb = blockIdx.y;
    const int* src = jb ? s1 : s0;
    const int* dst = jb ? d1 : d0;
    float* agg = jb ? a1 : a0;
    const int ldc = jb ? l1 : l0;
    const int off = jb ? o1 : o0;
    int s = __ldg(&src[warp]);
    int d = __ldg(&dst[warp]);
    const int c0 = lane * 4;
    float4 v = *reinterpret_cast<const float4*>(h + (size_t)s * EMB + c0);
    if (coef) {
        float4 ca = *reinterpret_cast<const float4*>(coef + c0);
        float4 cb = *reinterpret_cast<const float4*>(coef + 128 + c0);
        v.x = fmaxf(ca.x * v.x + cb.x, 0.f);
        v.y = fmaxf(ca.y * v.y + cb.y, 0.f);
        v.z = fmaxf(ca.z * v.z + cb.z, 0.f);
        v.w = fmaxf(ca.w * v.w + cb.w, 0.f);
    }
    red_add_v4(agg + (size_t)d * ldc + off + c0, v);
}

// ---------------- weight prep ----------------
__global__ void k_prep(const float* __restrict__ B1, const float* __restrict__ B2,
                       int Kb, int K, int Ngm, int Nout, float s1, float s2,
                       const float* __restrict__ b1, const float* __restrict__ b2,
                       __nv_bfloat16* __restrict__ oh, __nv_bfloat16* __restrict__ ol,
                       float* __restrict__ ob) {
    const int tot = Nout * K;
    for (int i = blockIdx.x * blockDim.x + threadIdx.x; i < tot;
         i += gridDim.x * blockDim.x) {
        int n = i / K, k = i - n * K;
        float v = (k < Kb) ? s1 * B1[(size_t)k * Ngm + n]
                           : s2 * B2[(size_t)(k - Kb) * Ngm + n];
        __nv_bfloat16 h = __float2bfloat16(v);
        oh[i] = h;
        ol[i] = __float2bfloat16(v - __bfloat162float(h));
        if (k == 0) ob[n] = s1 * b1[n] + s2 * b2[n];
    }
}

// ---------------- warp-MMA split-bf16 GEMM (legacy HMMA path), dual-job ----------------
__device__ __forceinline__ uint32_t s2u(const void* p) {
    uint32_t a;
    asm("{ .reg .u64 t; cvta.to.shared.u64 t, %1; cvt.u32.u64 %0, t; }"
        : "=r"(a) : "l"(p));
    return a;
}
__device__ __forceinline__ void ldsm4(uint32_t* r, uint32_t addr) {
    asm volatile("ldmatrix.sync.aligned.m8n8.x4.shared.b16 {%0,%1,%2,%3}, [%4];"
                 : "=r"(r[0]), "=r"(r[1]), "=r"(r[2]), "=r"(r[3]) : "r"(addr));
}
__device__ __forceinline__ void mma16816(float* c, const uint32_t* a, const uint32_t* b) {
    asm volatile(
        "mma.sync.aligned.m16n8k16.row.col.f32.bf16.bf16.f32 "
        "{%0,%1,%2,%3}, {%4,%5,%6,%7}, {%8,%9}, {%0,%1,%2,%3};"
        : "+f"(c[0]), "+f"(c[1]), "+f"(c[2]), "+f"(c[3])
        : "r"(a[0]), "r"(a[1]), "r"(a[2]), "r"(a[3]), "r"(b[0]), "r"(b[1]));
}
__device__ __forceinline__ uint32_t pk2(float a, float b) {
    __nv_bfloat162 h = __floats2bfloat162_rn(a, b);
    return *reinterpret_cast<uint32_t*>(&h);
}

struct GJob {
    const float* A; int lda, K;
    const __nv_bfloat16* Bh; const __nv_bfloat16* Bl;
    const float* biasc;
    float* C; int ldc, relu, nx;
};

__global__ __launch_bounds__(256, 2) void k_mma_gemm(GJob j0, GJob j1) {
    const GJob& j = blockIdx.z ? j1 : j0;
    if ((int)blockIdx.x >= j.nx) return;
    const float* __restrict__ A = j.A;
    const __nv_bfloat16* __restrict__ Bh = j.Bh;
    const __nv_bfloat16* __restrict__ Bl = j.Bl;
    const int lda = j.lda, K = j.K, ldc = j.ldc, relu = j.relu;
    const int M = N_NODE;

    __shared__ __nv_bfloat16 sAh[128 * PITCH], sAl[128 * PITCH];
    __shared__ __nv_bfloat16 sBh[128 * PITCH], sBl[128 * PITCH];
    const int t = threadIdx.x, lane = t & 31, wid = t >> 5;
    const int rowBase = blockIdx.y * 128;
    const int n0g = blockIdx.x * 128;
    const int wm = (wid >> 1) * 32, wn = (wid & 1) * 64;
    const uint32_t uAh = s2u(sAh), uAl = s2u(sAl);
    const uint32_t uBh = s2u(sBh), uBl = s2u(sBl);

    float acc[2][8][4];
#pragma unroll
    for (int i = 0; i < 2; i++)
#pragma unroll
        for (int jj = 0; jj < 8; jj++)
#pragma unroll
            for (int q = 0; q < 4; q++) acc[i][jj][q] = 0.f;

    const int li = lane & 7;
    const int a_row = (lane >> 3 & 1) * 8 + li;
    const int a_kof = (lane >> 4) * 8;
    const int b_nsel = lane >> 4;
    const int b_kof = ((lane >> 3) & 1) * 8;
    const int arow = t >> 1, acol = (t & 1) * 16;

    for (int k0 = 0; k0 < K; k0 += 32) {
        {
            const int gr = rowBase + arow;
            float f[16];
            if (gr < M) {
                const float* ap = A + (size_t)gr * lda + k0 + acol;
#pragma unroll
                for (int q = 0; q < 4; q++) {
                    float4 v = __ldg(reinterpret_cast<const float4*>(ap + q * 4));
                    f[4 * q] = v.x; f[4 * q + 1] = v.y;
                    f[4 * q + 2] = v.z; f[4 * q + 3] = v.w;
                }
            } else {
#pragma unroll
                for (int q = 0; q < 16; q++) f[q] = 0.f;
            }
            uint32_t h[8], l[8];
#pragma unroll
            for (int q = 0; q < 8; q++) {
                float x0 = f[2 * q], x1 = f[2 * q + 1];
                float r0 = x0 - __bfloat162float(__float2bfloat16(x0));
                float r1 = x1 - __bfloat162float(__float2bfloat16(x1));
                h[q] = pk2(x0, x1);
                l[q] = pk2(r0, r1);
            }
            __nv_bfloat16* dh = sAh + arow * PITCH + acol;
            __nv_bfloat16* dl = sAl + arow * PITCH + acol;
            reinterpret_cast<uint4*>(dh)[0] = make_uint4(h[0], h[1], h[2], h[3]);
            reinterpret_cast<uint4*>(dh)[1] = make_uint4(h[4], h[5], h[6], h[7]);
            reinterpret_cast<uint4*>(dl)[0] = make_uint4(l[0], l[1], l[2], l[3]);
            reinterpret_cast<uint4*>(dl)[1] = make_uint4(l[4], l[5], l[6], l[7]);
        }
        {
            const int brow = t >> 1, bcol = (t & 1) * 16;
            const size_t go = (size_t)(n0g + brow) * K + k0 + bcol;
            const uint4* bhp = reinterpret_cast<const uint4*>(Bh + go);
            const uint4* blp = reinterpret_cast<const uint4*>(Bl + go);
            __nv_bfloat16* dh = sBh + brow * PITCH + bcol;
            __nv_bfloat16* dl = sBl + brow * PITCH + bcol;
            reinterpret_cast<uint4*>(dh)[0] = __ldg(bhp);
            reinterpret_cast<uint4*>(dh)[1] = __ldg(bhp + 1);
            reinterpret_cast<uint4*>(dl)[0] = __ldg(blp);
            reinterpret_cast<uint4*>(dl)[1] = __ldg(blp + 1);
        }
        __syncthreads();

#pragma unroll
        for (int ks = 0; ks < 32; ks += 16) {
            uint32_t ah[2][4], al[2][4];
#pragma unroll
            for (int mt = 0; mt < 2; mt++) {
                uint32_t off = ((wm + mt * 16 + a_row) * PITCH + ks + a_kof) * 2;
                ldsm4(ah[mt], uAh + off);
                ldsm4(al[mt], uAl + off);
            }
#pragma unroll
            for (int np = 0; np < 4; np++) {
                uint32_t bh[4], bl[4];
                uint32_t off =
                    ((wn + (np * 2 + b_nsel) * 8 + li) * PITCH + ks + b_kof) * 2;
                ldsm4(bh, uBh + off);
                ldsm4(bl, uBl + off);
#pragma unroll
                for (int mt = 0; mt < 2; mt++) {
                    mma16816(acc[mt][2 * np], ah[mt], bh);
                    mma16816(acc[mt][2 * np], ah[mt], bl);
                    mma16816(acc[mt][2 * np], al[mt], bh);
                    mma16816(acc[mt][2 * np + 1], ah[mt], bh + 2);
                    mma16816(acc[mt][2 * np + 1], ah[mt], bl + 2);
                    mma16816(acc[mt][2 * np + 1], al[mt], bh + 2);
                }
            }
        }
        __syncthreads();
    }

    const int r4 = lane >> 2, c2 = (lane & 3) * 2;
#pragma unroll
    for (int mt = 0; mt < 2; mt++) {
        const int row0 = rowBase + wm + mt * 16 + r4;
        const int row1 = row0 + 8;
#pragma unroll
        for (int nt = 0; nt < 8; nt++) {
            const int col = n0g + wn + nt * 8 + c2;
            float b0 = __ldg(j.biasc + col), b1 = __ldg(j.biasc + col + 1);
            float v0 = acc[mt][nt][0] + b0, v1 = acc[mt][nt][1] + b1;
            float v2 = acc[mt][nt][2] + b0, v3 = acc[mt][nt][3] + b1;
            if (relu) {
                v0 = fmaxf(v0, 0.f); v1 = fmaxf(v1, 0.f);
                v2 = fmaxf(v2, 0.f); v3 = fmaxf(v3, 0.f);
            }
            if (row0 < M)
                *reinterpret_cast<float2*>(j.C + (size_t)row0 * ldc + col) =
                    make_float2(v0, v1);
            if (row1 < M)
                *reinterpret_cast<float2*>(j.C + (size_t)row1 * ldc + col) =
                    make_float2(v2, v3);
        }
    }
}

// ---------------- BatchNorm ----------------
__global__ void k_bn_stats2(const float* __restrict__ X0, const float* __restrict__ X1,
                            float* __restrict__ stats) {
    const float* X = blockIdx.y ? X1 : X0;
    float* st = stats + blockIdx.y * 256;
    const int col = threadIdx.x & 127;
    const int rp = threadIdx.x >> 7;
    float s = 0.f, q = 0.f;
    for (int r = blockIdx.x * 2 + rp; r < N_NODE; r += gridDim.x * 2) {
        float v = X[(size_t)r * EMB + col];
        s += v; q += v * v;
    }
    atomicAdd(&st[col], s);
    atomicAdd(&st[EMB + col], q);
}

__global__ void k_bn_finalize(float* __restrict__ stats, const float* __restrict__ gamma,
                              const float* __restrict__ beta, int layer, float invM) {
    int c = threadIdx.x;
    int type = c >> 7, col = c & 127;
    float mu = stats[type * 256 + col] * invM;
    float var = stats[type * 256 + 128 + col] * invM - mu * mu;
    float a = gamma[layer * EMB + col] * rsqrtf(var + 1e-5f);
    float b = beta[layer * EMB + col] - a * mu;
    stats[512 + type * 256 + col] = a;
    stats[512 + type * 256 + 128 + col] = b;
}

__global__ void k_bn_apply2(const float* __restrict__ X0, float* __restrict__ Y0,
                            const float* __restrict__ X1, float* __restrict__ Y1,
                            const float* __restrict__ stats, int relu) {
    const int n = N_NODE * EMB;
    for (int i = blockIdx.x * blockDim.x + threadIdx.x; i < 2 * n;
         i += gridDim.x * blockDim.x) {
        int col = i & 127;
        if (i < n) {
            float v = stats[512 + col] * X0[i] + stats[512 + 128 + col];
            if (relu) v = fmaxf(v, 0.f);
            Y0[i] = v;
        } else {
            int j = i - n;
            float v = stats[768 + col] * X1[j] + stats[768 + 128 + col];
            if (relu) v = fmaxf(v, 0.f);
            Y1[j] = v;
        }
    }
}

// ---------------- host orchestration ----------------
extern "C" void kernel_launch(void* const* d_in, const int* in_sizes, int n_in,
                              void* d_out, int out_size) {
    (void)in_sizes; (void)n_in; (void)out_size;
    const float* x0   = (const float*)d_in[0];
    const float* x1   = (const float*)d_in[1];
    const float* ea11 = (const float*)d_in[2];
    const float* ea10 = (const float*)d_in[3];
    const float* ea01 = (const float*)d_in[4];
    const float* ea00 = (const float*)d_in[5];
    const int*   ei11 = (const int*)d_in[6];
    const int*   ei10 = (const int*)d_in[7];
    const int*   ei01 = (const int*)d_in[8];
    const int*   ei00 = (const int*)d_in[9];
    const float* Wx  = (const float*)d_in[10];
    const float* bx  = (const float*)d_in[11];
    const float* We  = (const float*)d_in[12];
    const float* be  = (const float*)d_in[13];
    const float* gW1 = (const float*)d_in[14];
    const float* gb1 = (const float*)d_in[15];
    const float* gW2 = (const float*)d_in[16];
    const float* gb2 = (const float*)d_in[17];
    const float* W10 = (const float*)d_in[18];
    const float* b10 = (const float*)d_in[19];
    const float* W01 = (const float*)d_in[20];
    const float* b01 = (const float*)d_in[21];
    const float* W00 = (const float*)d_in[22];
    const float* b00 = (const float*)d_in[23];
    const float* gamma = (const float*)d_in[24];
    const float* beta  = (const float*)d_in[25];
    float* out = (float*)d_out;

    float *h0, *h1, *n0b, *n1b, *a11, *cat0, *cat1;
    float *esum, *deg, *stats, *biasc;
    __nv_bfloat16 *bth, *btl;
    cudaGetSymbolAddress((void**)&h0,   g_h0);
    cudaGetSymbolAddress((void**)&h1,   g_h1);
    cudaGetSymbolAddress((void**)&n0b,  g_n0);
    cudaGetSymbolAddress((void**)&n1b,  g_n1);
    cudaGetSymbolAddress((void**)&a11,  g_a11);
    cudaGetSymbolAddress((void**)&cat0, g_cat0);
    cudaGetSymbolAddress((void**)&cat1, g_cat1);
    cudaGetSymbolAddress((void**)&esum, g_esum);
    cudaGetSymbolAddress((void**)&deg,  g_deg);
    cudaGetSymbolAddress((void**)&stats, g_stats);
    cudaGetSymbolAddress((void**)&bth,  g_bth);
    cudaGetSymbolAddress((void**)&btl,  g_btl);
    cudaGetSymbolAddress((void**)&biasc, g_biasc);

    // ---- weight prep ----
    k_prep<<<128, 256>>>(Wx, Wx, 256, 256, 128, 128, 1.f, 0.f, bx, bx,
                         bth, btl, biasc);
    k_prep<<<128, 256>>>(gW1, gW1, 128, 128, 256, 256, 1.f, 0.f, gb1, gb1,
                         bth + 32768, btl + 32768, biasc + 256);
    k_prep<<<192, 256>>>(gW2, W01, 256, 384, 128, 128, 0.5f, 0.05f, gb2, b01,
                         bth + 65536, btl + 65536, biasc + 512);
    k_prep<<<128, 256>>>(W10, W00, 128, 256, 128, 128, 0.05f, 0.05f, b10, b00,
                         bth + 114688, btl + 114688, biasc + 768);

    // ---- edge phase: 16-wide sums + degree only (GEMV fused into layer init) ----
    k_zero<<<2048, 256>>>(esum, 4 * N_NODE * 4);
    k_zero<<<512, 256>>>(deg, N_NODE);
    {
        dim3 ge(512, 4);
        k_edge_sum4<<<ge, 256>>>(ea11, ei11 + N_EDGE, ea01, ei01 + N_EDGE,
                                 ea10, ei10 + N_EDGE, ea00, ei00 + N_EDGE,
                                 esum, deg);
    }

    const int MT = (N_NODE + 127) / 128;   // 782 row tiles

    // GEMM job configs
    GJob jX0 = {x0, 256, 256, bth, btl, biasc, h0, 128, 0, 1};
    GJob jX1 = {x1, 256, 256, bth, btl, biasc, h1, 128, 0, 1};
    GJob jT  = {a11, 128, 128, bth + 32768, btl + 32768, biasc + 256,
                cat1, 384, 1, 2};
    GJob jN1 = {cat1, 384, 384, bth + 65536, btl + 65536, biasc + 512,
                nullptr, 128, 0, 1};
    GJob jN0 = {cat0, 256, 256, bth + 114688, btl + 114688, biasc + 768,
                nullptr, 128, 0, 1};

    // Input embeddings (merged pair)
    {
        dim3 g(1, MT, 2);
        k_mma_gemm<<<g, 256>>>(jX0, jX1);
    }

    const int sgrid = (N_EDGE * 32) / 256;  // 1 warp per edge
    float* cur0 = h0;
    float* cur1 = h1;

    for (int layer = 0; layer < 2; layer++) {
        float* o0 = (layer == 0) ? n0b : h0;
        float* o1 = (layer == 0) ? n1b : h1;
        const float* c0p = (layer == 0) ? nullptr : stats + 512;
        const float* c1p = (layer == 0) ? nullptr : stats + 768;

        // fused init: 4-type edge GEMV from esum + GIN self-term
        k_init_gemv<<<1024, 256>>>(esum, deg, We, be, cat0, cat1, a11, cur1, c1p);

        // merged scatters: h1-sourced pair, then h0-sourced pair
        {
            dim3 gs(sgrid, 2);
            k_scatter2<<<gs, 256>>>(cur1,
                                    ei11, ei11 + N_EDGE, a11, 128, 0,
                                    ei10, ei10 + N_EDGE, cat0, 256, 0, c1p);
            k_scatter2<<<gs, 256>>>(cur0,
                                    ei01, ei01 + N_EDGE, cat1, 384, 256,
                                    ei00, ei00 + N_EDGE, cat0, 256, 128, c0p);
        }

        // merged GEMMs: T (nx=2) + new0 (nx=1); then new1
        jN0.C = o0;
        jN1.C = o1;
        {
            dim3 g(2, MT, 2);
            k_mma_gemm<<<g, 256>>>(jT, jN0);
        }
        {
            dim3 g(1, MT, 1);
            k_mma_gemm<<<g, 256>>>(jN1, jN1);
        }

        // BatchNorm stats + finalize
        k_zero<<<1, 128>>>(stats, 128);
        {
            dim3 gs(1024, 2);
            k_bn_stats2<<<gs, 256>>>(o0, o1, stats);
        }
        k_bn_finalize<<<1, 256>>>(stats, gamma, beta, layer, 1.f / N_NODE);

        // layer 0: BN apply fused into layer-1 consumers; layer 1: final apply
        if (layer == 1)
            k_bn_apply2<<<2048, 256>>>(h0, out, h1, out + (size_t)N_NODE * EMB,
                                       stats, 0);

        cur0 = o0;
        cur1 = o1;
    }
}